// round 13
// baseline (speedup 1.0000x reference)
#include <cuda_runtime.h>
#include <cuda_bf16.h>
#include <cstdint>
#include <cstddef>

#define NPTS 4096
#define NBATCH 8
#define BNODES (NBATCH * NPTS)   // 32768
#define KNN 5
#define NCH 8
#define CHSZ (NPTS / NCH)        // 512

typedef __nv_bfloat16 bf16;

// ---------------- scratch (static device globals; no runtime alloc) ----------------
__device__ __align__(256) float g_pts_sorted[BNODES * 3];
__device__ __align__(256) float g_sq[BNODES];
__device__ __align__(256) float g_dcent[BNODES];
__device__ __align__(256) int   g_nbr[BNODES * KNN];
__device__ __align__(256) int   g_deg[BNODES];
__device__ __align__(256) float g_norm[BNODES];
__device__ __align__(256) float g_kd[(size_t)BNODES * NCH * KNN];
__device__ __align__(256) int   g_kj[(size_t)BNODES * NCH * KNN];
__device__ __align__(256) float g_bufA[(size_t)BNODES * 256];
__device__ __align__(256) bf16  g_xh[(size_t)BNODES * 512];
__device__ __align__(256) bf16  g_xl[(size_t)BNODES * 512];
__device__ __align__(256) bf16  g_yh[(size_t)BNODES * 512];
__device__ __align__(256) bf16  g_yl[(size_t)BNODES * 512];
__device__ __align__(256) bf16  g_wh[344064];
__device__ __align__(256) bf16  g_wl[344064];
__device__ __align__(256) unsigned g_pool[256];

// weight offsets (elements, [N][K] layout)
#define OFF_W2  0
#define OFF_W3  4096
#define OFF_W4  8192
#define OFF_GC1 16384
#define OFF_GC2 32768
#define OFF_GC3 49152
#define OFF_FC1 81920
#define OFF_FC2 212992

// ================= helpers =================
__device__ __forceinline__ uint32_t smem_u32(const void* p) {
    uint32_t a;
    asm("{ .reg .u64 t; cvta.to.shared.u64 t, %1; cvt.u32.u64 %0, t; }" : "=r"(a) : "l"(p));
    return a;
}
#define SW128(off) ((off) ^ (((off) >> 3) & 0x70))

__device__ __forceinline__ void cp16(uint32_t saddr, const void* gptr) {
    asm volatile("cp.async.cg.shared.global [%0], [%1], 16;" :: "r"(saddr), "l"(gptr));
}
#define CP_COMMIT() asm volatile("cp.async.commit_group;" ::: "memory")
#define CP_WAIT0()  asm volatile("cp.async.wait_group 0;" ::: "memory")

__device__ __forceinline__ void ldsm_x4(uint32_t* r, uint32_t addr) {
    asm volatile("ldmatrix.sync.aligned.m8n8.x4.shared.b16 {%0,%1,%2,%3}, [%4];"
                 : "=r"(r[0]), "=r"(r[1]), "=r"(r[2]), "=r"(r[3]) : "r"(addr));
}
__device__ __forceinline__ void ldsm_x2(uint32_t* r, uint32_t addr) {
    asm volatile("ldmatrix.sync.aligned.m8n8.x2.shared.b16 {%0,%1}, [%2];"
                 : "=r"(r[0]), "=r"(r[1]) : "r"(addr));
}
__device__ __forceinline__ void mma16816(float* d, const uint32_t* a, const uint32_t* b) {
    asm volatile(
        "mma.sync.aligned.m16n8k16.row.col.f32.bf16.bf16.f32 "
        "{%0,%1,%2,%3}, {%4,%5,%6,%7}, {%8,%9}, {%0,%1,%2,%3};"
        : "+f"(d[0]), "+f"(d[1]), "+f"(d[2]), "+f"(d[3])
        : "r"(a[0]), "r"(a[1]), "r"(a[2]), "r"(a[3]), "r"(b[0]), "r"(b[1]));
}

__device__ __forceinline__ void split2(float f0, float f1, uint32_t& hi, uint32_t& lo) {
    bf16 h0 = __float2bfloat16(f0), h1 = __float2bfloat16(f1);
    float r0 = f0 - __bfloat162float(h0);
    float r1 = f1 - __bfloat162float(h1);
    bf16 l0 = __float2bfloat16(r0), l1 = __float2bfloat16(r1);
    hi = ((uint32_t)__bfloat16_as_ushort(h1) << 16) | (uint32_t)__bfloat16_as_ushort(h0);
    lo = ((uint32_t)__bfloat16_as_ushort(l1) << 16) | (uint32_t)__bfloat16_as_ushort(l0);
}

// ---------------- init ----------------
__global__ void init_kernel() {
    int i = blockIdx.x * blockDim.x + threadIdx.x;
    if (i < BNODES) g_deg[i] = 0;
    if (i < 256) g_pool[i] = 0u;
}

// ---------------- fused weight pre-split (one launch, 8 segments) ----------------
struct WSegs {
    const float* src[8];
    int dst[8], K[8], N[8], trans[8], cnt[8];
};
__global__ void wprep_all(WSegs S) {
    int o = blockIdx.x * blockDim.x + threadIdx.x;
    #pragma unroll
    for (int s = 0; s < 8; s++) {
        if (o < S.cnt[s]) {
            int K = S.K[s];
            int n = o / K, k = o - n * K;
            float f = S.trans[s] ? S.src[s][k * S.N[s] + n] : S.src[s][o];
            bf16 h = __float2bfloat16(f);
            g_wh[S.dst[s] + o] = h;
            g_wl[S.dst[s] + o] = __float2bfloat16(f - __bfloat162float(h));
            return;
        }
        o -= S.cnt[s];
    }
}

// ---------------- centroid + sq + d_cent ----------------
__global__ void prep_kernel(const float* __restrict__ pts) {
    int b = blockIdx.x;
    int tid = threadIdx.x;
    const float* p = pts + (size_t)b * 3 * NPTS;
    float sx = 0.f, sy = 0.f, sz = 0.f;
    for (int n = tid; n < NPTS; n += 256) {
        sx += p[n];
        sy += p[NPTS + n];
        sz += p[2 * NPTS + n];
    }
    __shared__ float rx[256], ry[256], rz[256];
    rx[tid] = sx; ry[tid] = sy; rz[tid] = sz;
    __syncthreads();
    for (int s = 128; s > 0; s >>= 1) {
        if (tid < s) { rx[tid] += rx[tid + s]; ry[tid] += ry[tid + s]; rz[tid] += rz[tid + s]; }
        __syncthreads();
    }
    __shared__ float cx, cy, cz;
    if (tid == 0) {
        cx = rx[0] / (float)NPTS;
        cy = ry[0] / (float)NPTS;
        cz = rz[0] / (float)NPTS;
    }
    __syncthreads();
    for (int n = tid; n < NPTS; n += 256) {
        float x = p[n], y = p[NPTS + n], z = p[2 * NPTS + n];
        g_sq[b * NPTS + n] = x * x + y * y + z * z;
        float dx = x - cx, dy = y - cy, dz = z - cz;
        g_dcent[b * NPTS + n] = dx * dx + dy * dy + dz * dz;
    }
}

// ---------------- stable argsort by rank counting (warp-cooperative, 8 pts/warp) ----------------
__global__ void sort_warp_kernel(const float* __restrict__ pts) {
    __shared__ float sd[NPTS];
    int b = blockIdx.x;
    int tid = threadIdx.x;
    for (int j = tid; j < NPTS; j += 256) sd[j] = g_dcent[b * NPTS + j];
    __syncthreads();
    int wid = tid >> 5, lane = tid & 31;
    int i_base = (blockIdx.y * 8 + wid) * 8;
    float di[8];
    int rank[8];
    #pragma unroll
    for (int q = 0; q < 8; q++) { di[q] = sd[i_base + q]; rank[q] = 0; }
    #pragma unroll 4
    for (int t = 0; t < 128; t++) {
        int j = lane + t * 32;
        float dj = sd[j];
        #pragma unroll
        for (int q = 0; q < 8; q++)
            rank[q] += (dj < di[q]) || (dj == di[q] && j < i_base + q);
    }
    #pragma unroll
    for (int q = 0; q < 8; q++) {
        #pragma unroll
        for (int off = 16; off; off >>= 1)
            rank[q] += __shfl_xor_sync(0xffffffffu, rank[q], off);
    }
    const float* p = pts + (size_t)b * 3 * NPTS;
    #pragma unroll
    for (int q = 0; q < 8; q++) {
        if (lane == q) {
            int i = i_base + q;
            int dst = (b * NPTS + rank[q]) * 3;
            g_pts_sorted[dst + 0] = p[i];
            g_pts_sorted[dst + 1] = p[NPTS + i];
            g_pts_sorted[dst + 2] = p[2 * NPTS + i];
        }
    }
}

// ---------------- KNN pass 1: per-(query, chunk) top-5 over 512 candidates ----------------
__global__ void knn_part_kernel(const float* __restrict__ pts) {
    __shared__ float4 cs[CHSZ];
    int b = blockIdx.x;
    int c = blockIdx.y >> 4;
    int qblk = blockIdx.y & 15;
    int tid = threadIdx.x;
    const float* p = pts + (size_t)b * 3 * NPTS;
    for (int j = tid; j < CHSZ; j += 256) {
        int jj = c * CHSZ + j;
        cs[j] = make_float4(p[jj], p[NPTS + jj], p[2 * NPTS + jj], g_sq[b * NPTS + jj]);
    }
    __syncthreads();
    int i = qblk * 256 + tid;
    float sqi = g_sq[b * NPTS + i];
    float qx = -2.0f * p[i], qy = -2.0f * p[NPTS + i], qz = -2.0f * p[2 * NPTS + i];

    float bd0 = 3.0e38f, bd1 = 3.0e38f, bd2 = 3.0e38f, bd3 = 3.0e38f, bd4 = 3.0e38f;
    int bj0 = 0x7fffffff, bj1 = 0x7fffffff, bj2 = 0x7fffffff, bj3 = 0x7fffffff, bj4 = 0x7fffffff;

    #pragma unroll 8
    for (int j = 0; j < CHSZ; j++) {
        float4 cj = cs[j];
        float d = fmaf(qx, cj.x, fmaf(qy, cj.y, fmaf(qz, cj.z, cj.w))) + sqi;
        if (d < bd4) {                      // strict <: earlier j wins ties (matches top_k)
            int jj = c * CHSZ + j;
            if (d < bd0) {
                bd4 = bd3; bj4 = bj3; bd3 = bd2; bj3 = bj2; bd2 = bd1; bj2 = bj1;
                bd1 = bd0; bj1 = bj0; bd0 = d; bj0 = jj;
            } else if (d < bd1) {
                bd4 = bd3; bj4 = bj3; bd3 = bd2; bj3 = bj2; bd2 = bd1; bj2 = bj1;
                bd1 = d; bj1 = jj;
            } else if (d < bd2) {
                bd4 = bd3; bj4 = bj3; bd3 = bd2; bj3 = bj2; bd2 = d; bj2 = jj;
            } else if (d < bd3) {
                bd4 = bd3; bj4 = bj3; bd3 = d; bj3 = jj;
            } else {
                bd4 = d; bj4 = jj;
            }
        }
    }
    size_t base = ((size_t)(b * NPTS + i) * NCH + c) * KNN;
    g_kd[base + 0] = bd0; g_kd[base + 1] = bd1; g_kd[base + 2] = bd2;
    g_kd[base + 3] = bd3; g_kd[base + 4] = bd4;
    g_kj[base + 0] = bj0; g_kj[base + 1] = bj1; g_kj[base + 2] = bj2;
    g_kj[base + 3] = bj3; g_kj[base + 4] = bj4;
}

// ---------------- KNN pass 2: merge 8 sorted 5-lists -> global top-5; count deg ----------------
__global__ void knn_merge_kernel() {
    int node = blockIdx.x * blockDim.x + threadIdx.x;
    int b = node >> 12;
    size_t base = (size_t)node * NCH * KNN;
    float hd[NCH];
    int hj[NCH], hp[NCH];
    #pragma unroll
    for (int c = 0; c < NCH; c++) {
        hd[c] = g_kd[base + c * KNN];
        hj[c] = g_kj[base + c * KNN];
        hp[c] = 0;
    }
    int out_base = node * KNN;
    int off = b * NPTS;
    #pragma unroll
    for (int r = 0; r < KNN; r++) {
        int best = 0;
        float d = hd[0];
        int j = hj[0];
        #pragma unroll
        for (int c = 1; c < NCH; c++) {
            if (hd[c] < d || (hd[c] == d && hj[c] < j)) { d = hd[c]; j = hj[c]; best = c; }
        }
        int nj = off + j;
        g_nbr[out_base + r] = nj;
        atomicAdd(&g_deg[nj], 1);
        int np = ++hp[best];
        if (np < KNN) {
            hd[best] = g_kd[base + best * KNN + np];
            hj[best] = g_kj[base + best * KNN + np];
        } else {
            hd[best] = 3.0e38f;
            hj[best] = 0x7fffffff;
        }
    }
}

__global__ void norm_kernel() {
    int i = blockIdx.x * blockDim.x + threadIdx.x;
    if (i < BNODES) g_norm[i] = rsqrtf(fmaxf((float)g_deg[i], 1.0f));
}

// ---------------- layer 1: 3 -> 64 pointwise + BN-affine + ReLU, split output ----------------
__global__ void layer1_kernel(const float* __restrict__ w1, const float* __restrict__ g1,
                              const float* __restrict__ b1) {
    int gid = blockIdx.x * blockDim.x + threadIdx.x;
    int node = gid >> 6;
    int o = gid & 63;
    const float* p = g_pts_sorted + node * 3;
    float a = p[0] * w1[o * 3 + 0] + p[1] * w1[o * 3 + 1] + p[2] * w1[o * 3 + 2];
    float v = fmaxf(a * g1[o] + b1[o], 0.0f);
    bf16 h = __float2bfloat16(v);
    size_t idx = (size_t)node * 64 + o;
    g_xh[idx] = h;
    g_xl[idx] = __float2bfloat16(v - __bfloat162float(h));
}

// ================= HMMA GEMM v3: cp.async pipelined, pre-split bf16 hi/lo =================
// OUT_MODE: 0 = fp32 C, 1 = split bf16 Ch/Cl, 2 = fused channel max-pool into g_pool.
// NSTAGE: smem pipeline stages (1 for K=64 single-chunk, 2 for K>=128).
template <int BN, int OUT_MODE, int NSTAGE>
__global__ void __launch_bounds__(256, 1)
hmma_gemm3(const bf16* __restrict__ Ah, const bf16* __restrict__ Al,
           const bf16* __restrict__ Wh, const bf16* __restrict__ Wl,
           float* __restrict__ C, bf16* __restrict__ Ch, bf16* __restrict__ Cl,
           int M, int N, int K,
           const float* __restrict__ gamma, const float* __restrict__ beta,
           const float* __restrict__ rowscale, int do_relu) {
    extern __shared__ char sm_raw[];
    __shared__ unsigned spool[128];
    uint32_t raw_s = smem_u32(sm_raw);
    uint32_t base_s = (raw_s + 1023u) & ~1023u;
    char* dsm = sm_raw + (base_s - raw_s);

    constexpr int ABYTES = 128 * 64 * 2;
    constexpr int BBYTES = BN * 64 * 2;
    constexpr int STAGE = 2 * ABYTES + 2 * BBYTES;
    constexpr int NI = BN / 32;
    constexpr int WN = BN / 4;

    int tid = threadIdx.x;
    int lane = tid & 31;
    int wid = tid >> 5;
    int wm = wid >> 2;
    int wn = wid & 3;
    int m0 = blockIdx.y * 128;
    int n0 = blockIdx.x * BN;

    if (OUT_MODE == 2 && tid < BN) spool[tid] = 0u;

    auto copy_chunk = [&](int cc, char* st) {
        char* pAh = st;
        char* pAl = pAh + ABYTES;
        char* pBh = pAl + ABYTES;
        char* pBl = pBh + BBYTES;
        int k0g = cc << 6;
        #pragma unroll
        for (int i = 0; i < 4; i++) {
            int g = tid + i * 256;
            int row = g >> 3, kg = g & 7;
            size_t src = (size_t)(m0 + row) * K + k0g + kg * 8;
            uint32_t off = SW128((uint32_t)(row * 128 + kg * 16));
            cp16(smem_u32(pAh + off), Ah + src);
            cp16(smem_u32(pAl + off), Al + src);
        }
        #pragma unroll
        for (int i = 0; i < (BN * 8) / 256; i++) {
            int g = tid + i * 256;
            int row = g >> 3, kg = g & 7;
            size_t src = (size_t)(n0 + row) * K + k0g + kg * 8;
            uint32_t off = SW128((uint32_t)(row * 128 + kg * 16));
            cp16(smem_u32(pBh + off), Wh + src);
            cp16(smem_u32(pBl + off), Wl + src);
        }
    };

    float acc[4][NI][4];
    #pragma unroll
    for (int mi = 0; mi < 4; mi++)
        #pragma unroll
        for (int ni = 0; ni < NI; ni++)
            #pragma unroll
            for (int r = 0; r < 4; r++) acc[mi][ni][r] = 0.0f;

    int nchunks = K >> 6;
    copy_chunk(0, dsm);
    CP_COMMIT();

    for (int c = 0; c < nchunks; c++) {
        char* st = dsm + (c % NSTAGE) * STAGE;
        if (NSTAGE == 1 && c > 0) { copy_chunk(c, st); CP_COMMIT(); }
        CP_WAIT0();
        __syncthreads();
        if (NSTAGE > 1 && c + 1 < nchunks) {
            copy_chunk(c + 1, dsm + ((c + 1) % NSTAGE) * STAGE);
            CP_COMMIT();
        }
        uint32_t sAh = smem_u32(st);
        uint32_t sAl = sAh + ABYTES;
        uint32_t sBh = sAl + ABYTES;
        uint32_t sBl = sBh + BBYTES;

        #pragma unroll
        for (int kk = 0; kk < 4; kk++) {
            int k0 = kk * 16;
            uint32_t aH[4][4], aL[4][4], bH[NI][2], bL[NI][2];
            #pragma unroll
            for (int mi = 0; mi < 4; mi++) {
                int row = wm * 64 + mi * 16 + (lane & 15);
                uint32_t off = SW128((uint32_t)(row * 128 + (k0 + ((lane >> 4) << 3)) * 2));
                ldsm_x4(aH[mi], sAh + off);
                ldsm_x4(aL[mi], sAl + off);
            }
            #pragma unroll
            for (int ni = 0; ni < NI; ni++) {
                int nrow = wn * WN + ni * 8 + (lane & 7);
                uint32_t off = SW128((uint32_t)(nrow * 128 + (k0 + (((lane >> 3) & 1) << 3)) * 2));
                ldsm_x2(bH[ni], sBh + off);
                ldsm_x2(bL[ni], sBl + off);
            }
            #pragma unroll
            for (int mi = 0; mi < 4; mi++)
                #pragma unroll
                for (int ni = 0; ni < NI; ni++) {
                    mma16816(acc[mi][ni], aH[mi], bH[ni]);
                    mma16816(acc[mi][ni], aH[mi], bL[ni]);
                    mma16816(acc[mi][ni], aL[mi], bH[ni]);
                }
        }
        __syncthreads();
    }

    // ---- epilogue ----
    float pmax[NI][2];
    if (OUT_MODE == 2) {
        #pragma unroll
        for (int ni = 0; ni < NI; ni++) { pmax[ni][0] = 0.0f; pmax[ni][1] = 0.0f; }
    }
    #pragma unroll
    for (int mi = 0; mi < 4; mi++) {
        int r0 = m0 + wm * 64 + mi * 16 + (lane >> 2);
        int r1 = r0 + 8;
        float rs0 = rowscale ? rowscale[r0] : 1.0f;
        float rs1 = rowscale ? rowscale[r1] : 1.0f;
        #pragma unroll
        for (int ni = 0; ni < NI; ni++) {
            int cN = n0 + wn * WN + ni * 8 + (lane & 3) * 2;
            float gm0 = 1.0f, gm1 = 1.0f, be0 = 0.0f, be1 = 0.0f;
            if (gamma) { gm0 = gamma[cN]; gm1 = gamma[cN + 1]; be0 = beta[cN]; be1 = beta[cN + 1]; }
            float x0 = acc[mi][ni][0] * rs0 * gm0 + be0;
            float x1 = acc[mi][ni][1] * rs0 * gm1 + be1;
            float x2 = acc[mi][ni][2] * rs1 * gm0 + be0;
            float x3 = acc[mi][ni][3] * rs1 * gm1 + be1;
            if (do_relu) {
                x0 = fmaxf(x0, 0.0f); x1 = fmaxf(x1, 0.0f);
                x2 = fmaxf(x2, 0.0f); x3 = fmaxf(x3, 0.0f);
            }
            if (OUT_MODE == 0) {
                *(float2*)(C + (size_t)r0 * N + cN) = make_float2(x0, x1);
                *(float2*)(C + (size_t)r1 * N + cN) = make_float2(x2, x3);
            } else if (OUT_MODE == 1) {
                uint32_t h01, l01, h23, l23;
                split2(x0, x1, h01, l01);
                split2(x2, x3, h23, l23);
                *(uint32_t*)(Ch + (size_t)r0 * N + cN) = h01;
                *(uint32_t*)(Cl + (size_t)r0 * N + cN) = l01;
                *(uint32_t*)(Ch + (size_t)r1 * N + cN) = h23;
                *(uint32_t*)(Cl + (size_t)r1 * N + cN) = l23;
            } else {
                pmax[ni][0] = fmaxf(pmax[ni][0], fmaxf(x0, x2));
                pmax[ni][1] = fmaxf(pmax[ni][1], fmaxf(x1, x3));
            }
        }
    }
    if (OUT_MODE == 2) {
        #pragma unroll
        for (int ni = 0; ni < NI; ni++) {
            int col = wn * WN + ni * 8 + (lane & 3) * 2;
            atomicMax(&spool[col], __float_as_uint(pmax[ni][0]));
            atomicMax(&spool[col + 1], __float_as_uint(pmax[ni][1]));
        }
        __syncthreads();
        if (tid < BN) atomicMax(&g_pool[n0 + tid], spool[tid]);
    }
}

// ---------------- GCN aggregate: split-output version ----------------
__global__ void agg_kernel(const float* __restrict__ hw, const float* __restrict__ bias,
                           bf16* __restrict__ Ch, bf16* __restrict__ Cl, int F, int do_relu) {
    size_t gid = (size_t)blockIdx.x * blockDim.x + threadIdx.x;
    int node = (int)(gid / F);
    int f = (int)(gid - (size_t)node * F);
    const int* nb = g_nbr + node * KNN;
    float s = hw[(size_t)nb[0] * F + f];
    s += hw[(size_t)nb[1] * F + f];
    s += hw[(size_t)nb[2] * F + f];
    s += hw[(size_t)nb[3] * F + f];
    s += hw[(size_t)nb[4] * F + f];
    float v = s * 0.44721359549995793f + bias[f];   // rsqrt(5) == norm_in (deg_in == 5 always)
    if (do_relu) v = fmaxf(v, 0.0f);
    bf16 h = __float2bfloat16(v);
    Ch[gid] = h;
    Cl[gid] = __float2bfloat16(v - __bfloat162float(h));
}

// ---------------- final linear 256 -> 128 ----------------
__global__ void final_kernel(const float* __restrict__ fc3_w, const float* __restrict__ fc3_b,
                             float* __restrict__ out) {
    int o = threadIdx.x;
    float s = 0.0f;
    #pragma unroll 8
    for (int k = 0; k < 256; k++)
        s += __uint_as_float(g_pool[k]) * fc3_w[o * 256 + k];
    out[o] = s + fc3_b[o];
}

// ---------------- orchestration ----------------
extern "C" void kernel_launch(void* const* d_in, const int* in_sizes, int n_in,
                              void* d_out, int out_size) {
    const float* pts  = (const float*)d_in[0];
    const float* w1   = (const float*)d_in[1];
    const float* g1   = (const float*)d_in[2];
    const float* b1   = (const float*)d_in[3];
    const float* w2   = (const float*)d_in[4];
    const float* g2   = (const float*)d_in[5];
    const float* b2   = (const float*)d_in[6];
    const float* w3   = (const float*)d_in[7];
    const float* g3   = (const float*)d_in[8];
    const float* b3   = (const float*)d_in[9];
    const float* w4   = (const float*)d_in[10];
    const float* g4   = (const float*)d_in[11];
    const float* b4   = (const float*)d_in[12];
    const float* gc1w = (const float*)d_in[13];
    const float* gc1b = (const float*)d_in[14];
    const float* gc2w = (const float*)d_in[15];
    const float* gc2b = (const float*)d_in[16];
    const float* gc3w = (const float*)d_in[17];
    const float* gc3b = (const float*)d_in[18];
    const float* fc1w = (const float*)d_in[19];
    const float* bf1g = (const float*)d_in[20];
    const float* bf1b = (const float*)d_in[21];
    const float* fc2w = (const float*)d_in[22];
    const float* bf2g = (const float*)d_in[23];
    const float* bf2b = (const float*)d_in[24];
    const float* fc3w = (const float*)d_in[25];
    const float* fc3b = (const float*)d_in[26];
    float* out = (float*)d_out;

    void* p;
    cudaGetSymbolAddress(&p, g_bufA);  float* bufA = (float*)p;
    cudaGetSymbolAddress(&p, g_norm);  float* normp = (float*)p;
    cudaGetSymbolAddress(&p, g_xh);    bf16* xh = (bf16*)p;
    cudaGetSymbolAddress(&p, g_xl);    bf16* xl = (bf16*)p;
    cudaGetSymbolAddress(&p, g_yh);    bf16* yh = (bf16*)p;
    cudaGetSymbolAddress(&p, g_yl);    bf16* yl = (bf16*)p;
    cudaGetSymbolAddress(&p, g_wh);    bf16* wh = (bf16*)p;
    cudaGetSymbolAddress(&p, g_wl);    bf16* wl = (bf16*)p;

    const int ST64  = 2 * 128 * 64 * 2 + 2 * 64 * 64 * 2;    // 49152
    const int ST128 = 2 * 128 * 64 * 2 + 2 * 128 * 64 * 2;   // 65536
    const int SM64_1  = ST64 + 1024;
    const int SM128_1 = ST128 + 1024;
    const int SM128_2 = 2 * ST128 + 1024;                     // 132096
    cudaFuncSetAttribute(hmma_gemm3<64, 1, 1>,  cudaFuncAttributeMaxDynamicSharedMemorySize, SM64_1);
    cudaFuncSetAttribute(hmma_gemm3<128, 1, 1>, cudaFuncAttributeMaxDynamicSharedMemorySize, SM128_1);
    cudaFuncSetAttribute(hmma_gemm3<128, 0, 2>, cudaFuncAttributeMaxDynamicSharedMemorySize, SM128_2);
    cudaFuncSetAttribute(hmma_gemm3<128, 1, 2>, cudaFuncAttributeMaxDynamicSharedMemorySize, SM128_2);
    cudaFuncSetAttribute(hmma_gemm3<128, 2, 2>, cudaFuncAttributeMaxDynamicSharedMemorySize, SM128_2);

    const int M = BNODES;

    init_kernel<<<(BNODES + 255) / 256, 256>>>();

    WSegs S;
    S.src[0] = w2;   S.dst[0] = OFF_W2;  S.K[0] = 64;  S.N[0] = 64;  S.trans[0] = 0; S.cnt[0] = 4096;
    S.src[1] = w3;   S.dst[1] = OFF_W3;  S.K[1] = 64;  S.N[1] = 64;  S.trans[1] = 0; S.cnt[1] = 4096;
    S.src[2] = w4;   S.dst[2] = OFF_W4;  S.K[2] = 64;  S.N[2] = 128; S.trans[2] = 0; S.cnt[2] = 8192;
    S.src[3] = gc1w; S.dst[3] = OFF_GC1; S.K[3] = 128; S.N[3] = 128; S.trans[3] = 1; S.cnt[3] = 16384;
    S.src[4] = gc2w; S.dst[4] = OFF_GC2; S.K[4] = 128; S.N[4] = 128; S.trans[4] = 1; S.cnt[4] = 16384;
    S.src[5] = gc3w; S.dst[5] = OFF_GC3; S.K[5] = 128; S.N[5] = 256; S.trans[5] = 1; S.cnt[5] = 32768;
    S.src[6] = fc1w; S.dst[6] = OFF_FC1; S.K[6] = 256; S.N[6] = 512; S.trans[6] = 0; S.cnt[6] = 131072;
    S.src[7] = fc2w; S.dst[7] = OFF_FC2; S.K[7] = 512; S.N[7] = 256; S.trans[7] = 0; S.cnt[7] = 131072;
    wprep_all<<<344064 / 256, 256>>>(S);

    prep_kernel<<<NBATCH, 256>>>(pts);
    sort_warp_kernel<<<dim3(NBATCH, NPTS / 64), 256>>>(pts);
    knn_part_kernel<<<dim3(NBATCH, 16 * NCH), 256>>>(pts);
    knn_merge_kernel<<<BNODES / 256, 256>>>();
    norm_kernel<<<(BNODES + 255) / 256, 256>>>();

    // local conv stack (split-in, split-out)
    layer1_kernel<<<(BNODES * 64) / 256, 256>>>(w1, g1, b1);
    hmma_gemm3<64, 1, 1><<<dim3(1, M / 128), 256, SM64_1>>>(
        xh, xl, wh + OFF_W2, wl + OFF_W2, nullptr, yh, yl, M, 64, 64, g2, b2, nullptr, 1);
    hmma_gemm3<64, 1, 1><<<dim3(1, M / 128), 256, SM64_1>>>(
        yh, yl, wh + OFF_W3, wl + OFF_W3, nullptr, xh, xl, M, 64, 64, g3, b3, nullptr, 1);
    hmma_gemm3<128, 1, 1><<<dim3(1, M / 128), 256, SM128_1>>>(
        xh, xl, wh + OFF_W4, wl + OFF_W4, nullptr, yh, yl, M, 128, 64, g4, b4, nullptr, 1);

    // GCN layers
    hmma_gemm3<128, 0, 2><<<dim3(1, M / 128), 256, SM128_2>>>(
        yh, yl, wh + OFF_GC1, wl + OFF_GC1, bufA, nullptr, nullptr, M, 128, 128, nullptr, nullptr, normp, 0);
    agg_kernel<<<(M * 128) / 256, 256>>>(bufA, gc1b, xh, xl, 128, 1);
    hmma_gemm3<128, 0, 2><<<dim3(1, M / 128), 256, SM128_2>>>(
        xh, xl, wh + OFF_GC2, wl + OFF_GC2, bufA, nullptr, nullptr, M, 128, 128, nullptr, nullptr, normp, 0);
    agg_kernel<<<(M * 128) / 256, 256>>>(bufA, gc2b, yh, yl, 128, 1);
    hmma_gemm3<128, 0, 2><<<dim3(2, M / 128), 256, SM128_2>>>(
        yh, yl, wh + OFF_GC3, wl + OFF_GC3, bufA, nullptr, nullptr, M, 256, 128, nullptr, nullptr, normp, 0);
    agg_kernel<<<(M * 256) / 256, 256>>>(bufA, gc3b, xh, xl, 256, 0);

    // head
    hmma_gemm3<128, 1, 2><<<dim3(4, M / 128), 256, SM128_2>>>(
        xh, xl, wh + OFF_FC1, wl + OFF_FC1, nullptr, yh, yl, M, 512, 256, bf1g, bf1b, nullptr, 1);
    hmma_gemm3<128, 2, 2><<<dim3(2, M / 128), 256, SM128_2>>>(
        yh, yl, wh + OFF_FC2, wl + OFF_FC2, nullptr, nullptr, nullptr, M, 256, 512, bf2g, bf2b, nullptr, 1);

    final_kernel<<<1, 128>>>(fc3w, fc3b, out);
}

// round 14
// speedup vs baseline: 1.0002x; 1.0002x over previous
#include <cuda_runtime.h>
#include <cuda_bf16.h>
#include <cstdint>
#include <cstddef>

#define NPTS 4096
#define NBATCH 8
#define BNODES (NBATCH * NPTS)   // 32768
#define KNN 5
#define NCH 8
#define CHSZ (NPTS / NCH)        // 512

typedef __nv_bfloat16 bf16;

// ---------------- scratch (static device globals; no runtime alloc) ----------------
__device__ __align__(256) float g_pts_sorted[BNODES * 3];
__device__ __align__(256) float g_sq[BNODES];
__device__ __align__(256) float g_dcent[BNODES];
__device__ __align__(256) int   g_nbr[BNODES * KNN];
__device__ __align__(256) int   g_deg[BNODES];
__device__ __align__(256) float g_norm[BNODES];
__device__ __align__(256) float g_kd[(size_t)BNODES * NCH * KNN];
__device__ __align__(256) int   g_kj[(size_t)BNODES * NCH * KNN];
__device__ __align__(256) float g_bufA[(size_t)BNODES * 256];
__device__ __align__(256) bf16  g_xh[(size_t)BNODES * 512];
__device__ __align__(256) bf16  g_xl[(size_t)BNODES * 512];
__device__ __align__(256) bf16  g_yh[(size_t)BNODES * 512];
__device__ __align__(256) bf16  g_yl[(size_t)BNODES * 512];
__device__ __align__(256) bf16  g_wh[344064];
__device__ __align__(256) bf16  g_wl[344064];
__device__ __align__(256) unsigned g_pool[256];

// weight offsets (elements, [N][K] layout)
#define OFF_W2  0
#define OFF_W3  4096
#define OFF_W4  8192
#define OFF_GC1 16384
#define OFF_GC2 32768
#define OFF_GC3 49152
#define OFF_FC1 81920
#define OFF_FC2 212992

// ================= helpers =================
__device__ __forceinline__ uint32_t smem_u32(const void* p) {
    uint32_t a;
    asm("{ .reg .u64 t; cvta.to.shared.u64 t, %1; cvt.u32.u64 %0, t; }" : "=r"(a) : "l"(p));
    return a;
}
#define SW128(off) ((off) ^ (((off) >> 3) & 0x70))

__device__ __forceinline__ void cp16(uint32_t saddr, const void* gptr) {
    asm volatile("cp.async.cg.shared.global [%0], [%1], 16;" :: "r"(saddr), "l"(gptr));
}
#define CP_COMMIT() asm volatile("cp.async.commit_group;" ::: "memory")
#define CP_WAIT0()  asm volatile("cp.async.wait_group 0;" ::: "memory")

__device__ __forceinline__ void ldsm_x4(uint32_t* r, uint32_t addr) {
    asm volatile("ldmatrix.sync.aligned.m8n8.x4.shared.b16 {%0,%1,%2,%3}, [%4];"
                 : "=r"(r[0]), "=r"(r[1]), "=r"(r[2]), "=r"(r[3]) : "r"(addr));
}
__device__ __forceinline__ void ldsm_x2(uint32_t* r, uint32_t addr) {
    asm volatile("ldmatrix.sync.aligned.m8n8.x2.shared.b16 {%0,%1}, [%2];"
                 : "=r"(r[0]), "=r"(r[1]) : "r"(addr));
}
__device__ __forceinline__ void mma16816(float* d, const uint32_t* a, const uint32_t* b) {
    asm volatile(
        "mma.sync.aligned.m16n8k16.row.col.f32.bf16.bf16.f32 "
        "{%0,%1,%2,%3}, {%4,%5,%6,%7}, {%8,%9}, {%0,%1,%2,%3};"
        : "+f"(d[0]), "+f"(d[1]), "+f"(d[2]), "+f"(d[3])
        : "r"(a[0]), "r"(a[1]), "r"(a[2]), "r"(a[3]), "r"(b[0]), "r"(b[1]));
}

__device__ __forceinline__ void split2(float f0, float f1, uint32_t& hi, uint32_t& lo) {
    bf16 h0 = __float2bfloat16(f0), h1 = __float2bfloat16(f1);
    float r0 = f0 - __bfloat162float(h0);
    float r1 = f1 - __bfloat162float(h1);
    bf16 l0 = __float2bfloat16(r0), l1 = __float2bfloat16(r1);
    hi = ((uint32_t)__bfloat16_as_ushort(h1) << 16) | (uint32_t)__bfloat16_as_ushort(h0);
    lo = ((uint32_t)__bfloat16_as_ushort(l1) << 16) | (uint32_t)__bfloat16_as_ushort(l0);
}

// ---------------- init ----------------
__global__ void init_kernel() {
    int i = blockIdx.x * blockDim.x + threadIdx.x;
    if (i < BNODES) g_deg[i] = 0;
    if (i < 256) g_pool[i] = 0u;
}

// ---------------- fused weight pre-split (one launch, 8 segments) ----------------
struct WSegs {
    const float* src[8];
    int dst[8], K[8], N[8], trans[8], cnt[8];
};
__global__ void wprep_all(WSegs S) {
    int o = blockIdx.x * blockDim.x + threadIdx.x;
    #pragma unroll
    for (int s = 0; s < 8; s++) {
        if (o < S.cnt[s]) {
            int K = S.K[s];
            int n = o / K, k = o - n * K;
            float f = S.trans[s] ? S.src[s][k * S.N[s] + n] : S.src[s][o];
            bf16 h = __float2bfloat16(f);
            g_wh[S.dst[s] + o] = h;
            g_wl[S.dst[s] + o] = __float2bfloat16(f - __bfloat162float(h));
            return;
        }
        o -= S.cnt[s];
    }
}

// ---------------- centroid + sq + d_cent ----------------
__global__ void prep_kernel(const float* __restrict__ pts) {
    int b = blockIdx.x;
    int tid = threadIdx.x;
    const float* p = pts + (size_t)b * 3 * NPTS;
    float sx = 0.f, sy = 0.f, sz = 0.f;
    for (int n = tid; n < NPTS; n += 256) {
        sx += p[n];
        sy += p[NPTS + n];
        sz += p[2 * NPTS + n];
    }
    __shared__ float rx[256], ry[256], rz[256];
    rx[tid] = sx; ry[tid] = sy; rz[tid] = sz;
    __syncthreads();
    for (int s = 128; s > 0; s >>= 1) {
        if (tid < s) { rx[tid] += rx[tid + s]; ry[tid] += ry[tid + s]; rz[tid] += rz[tid + s]; }
        __syncthreads();
    }
    __shared__ float cx, cy, cz;
    if (tid == 0) {
        cx = rx[0] / (float)NPTS;
        cy = ry[0] / (float)NPTS;
        cz = rz[0] / (float)NPTS;
    }
    __syncthreads();
    for (int n = tid; n < NPTS; n += 256) {
        float x = p[n], y = p[NPTS + n], z = p[2 * NPTS + n];
        g_sq[b * NPTS + n] = x * x + y * y + z * z;
        float dx = x - cx, dy = y - cy, dz = z - cz;
        g_dcent[b * NPTS + n] = dx * dx + dy * dy + dz * dz;
    }
}

// ---------------- stable argsort by rank counting (warp-cooperative, 8 pts/warp) ----------------
__global__ void sort_warp_kernel(const float* __restrict__ pts) {
    __shared__ float sd[NPTS];
    int b = blockIdx.x;
    int tid = threadIdx.x;
    for (int j = tid; j < NPTS; j += 256) sd[j] = g_dcent[b * NPTS + j];
    __syncthreads();
    int wid = tid >> 5, lane = tid & 31;
    int i_base = (blockIdx.y * 8 + wid) * 8;
    float di[8];
    int rank[8];
    #pragma unroll
    for (int q = 0; q < 8; q++) { di[q] = sd[i_base + q]; rank[q] = 0; }
    #pragma unroll 4
    for (int t = 0; t < 128; t++) {
        int j = lane + t * 32;
        float dj = sd[j];
        #pragma unroll
        for (int q = 0; q < 8; q++)
            rank[q] += (dj < di[q]) || (dj == di[q] && j < i_base + q);
    }
    #pragma unroll
    for (int q = 0; q < 8; q++) {
        #pragma unroll
        for (int off = 16; off; off >>= 1)
            rank[q] += __shfl_xor_sync(0xffffffffu, rank[q], off);
    }
    const float* p = pts + (size_t)b * 3 * NPTS;
    #pragma unroll
    for (int q = 0; q < 8; q++) {
        if (lane == q) {
            int i = i_base + q;
            int dst = (b * NPTS + rank[q]) * 3;
            g_pts_sorted[dst + 0] = p[i];
            g_pts_sorted[dst + 1] = p[NPTS + i];
            g_pts_sorted[dst + 2] = p[2 * NPTS + i];
        }
    }
}

// ---------------- KNN pass 1: per-(query, chunk) top-5 over 512 candidates ----------------
__global__ void knn_part_kernel(const float* __restrict__ pts) {
    __shared__ float4 cs[CHSZ];
    int b = blockIdx.x;
    int c = blockIdx.y >> 4;
    int qblk = blockIdx.y & 15;
    int tid = threadIdx.x;
    const float* p = pts + (size_t)b * 3 * NPTS;
    for (int j = tid; j < CHSZ; j += 256) {
        int jj = c * CHSZ + j;
        cs[j] = make_float4(p[jj], p[NPTS + jj], p[2 * NPTS + jj], g_sq[b * NPTS + jj]);
    }
    __syncthreads();
    int i = qblk * 256 + tid;
    float sqi = g_sq[b * NPTS + i];
    float qx = -2.0f * p[i], qy = -2.0f * p[NPTS + i], qz = -2.0f * p[2 * NPTS + i];

    float bd0 = 3.0e38f, bd1 = 3.0e38f, bd2 = 3.0e38f, bd3 = 3.0e38f, bd4 = 3.0e38f;
    int bj0 = 0x7fffffff, bj1 = 0x7fffffff, bj2 = 0x7fffffff, bj3 = 0x7fffffff, bj4 = 0x7fffffff;

    #pragma unroll 8
    for (int j = 0; j < CHSZ; j++) {
        float4 cj = cs[j];
        float d = fmaf(qx, cj.x, fmaf(qy, cj.y, fmaf(qz, cj.z, cj.w))) + sqi;
        if (d < bd4) {                      // strict <: earlier j wins ties (matches top_k)
            int jj = c * CHSZ + j;
            if (d < bd0) {
                bd4 = bd3; bj4 = bj3; bd3 = bd2; bj3 = bj2; bd2 = bd1; bj2 = bj1;
                bd1 = bd0; bj1 = bj0; bd0 = d; bj0 = jj;
            } else if (d < bd1) {
                bd4 = bd3; bj4 = bj3; bd3 = bd2; bj3 = bj2; bd2 = bd1; bj2 = bj1;
                bd1 = d; bj1 = jj;
            } else if (d < bd2) {
                bd4 = bd3; bj4 = bj3; bd3 = bd2; bj3 = bj2; bd2 = d; bj2 = jj;
            } else if (d < bd3) {
                bd4 = bd3; bj4 = bj3; bd3 = d; bj3 = jj;
            } else {
                bd4 = d; bj4 = jj;
            }
        }
    }
    size_t base = ((size_t)(b * NPTS + i) * NCH + c) * KNN;
    g_kd[base + 0] = bd0; g_kd[base + 1] = bd1; g_kd[base + 2] = bd2;
    g_kd[base + 3] = bd3; g_kd[base + 4] = bd4;
    g_kj[base + 0] = bj0; g_kj[base + 1] = bj1; g_kj[base + 2] = bj2;
    g_kj[base + 3] = bj3; g_kj[base + 4] = bj4;
}

// ---------------- KNN pass 2: merge 8 sorted 5-lists -> global top-5; count deg ----------------
__global__ void knn_merge_kernel() {
    int node = blockIdx.x * blockDim.x + threadIdx.x;
    int b = node >> 12;
    size_t base = (size_t)node * NCH * KNN;
    float hd[NCH];
    int hj[NCH], hp[NCH];
    #pragma unroll
    for (int c = 0; c < NCH; c++) {
        hd[c] = g_kd[base + c * KNN];
        hj[c] = g_kj[base + c * KNN];
        hp[c] = 0;
    }
    int out_base = node * KNN;
    int off = b * NPTS;
    #pragma unroll
    for (int r = 0; r < KNN; r++) {
        int best = 0;
        float d = hd[0];
        int j = hj[0];
        #pragma unroll
        for (int c = 1; c < NCH; c++) {
            if (hd[c] < d || (hd[c] == d && hj[c] < j)) { d = hd[c]; j = hj[c]; best = c; }
        }
        int nj = off + j;
        g_nbr[out_base + r] = nj;
        atomicAdd(&g_deg[nj], 1);
        int np = ++hp[best];
        if (np < KNN) {
            hd[best] = g_kd[base + best * KNN + np];
            hj[best] = g_kj[base + best * KNN + np];
        } else {
            hd[best] = 3.0e38f;
            hj[best] = 0x7fffffff;
        }
    }
}

__global__ void norm_kernel() {
    int i = blockIdx.x * blockDim.x + threadIdx.x;
    if (i < BNODES) g_norm[i] = rsqrtf(fmaxf((float)g_deg[i], 1.0f));
}

// ---------------- layer 1: 3 -> 64 pointwise + BN-affine + ReLU, split output ----------------
__global__ void layer1_kernel(const float* __restrict__ w1, const float* __restrict__ g1,
                              const float* __restrict__ b1) {
    int gid = blockIdx.x * blockDim.x + threadIdx.x;
    int node = gid >> 6;
    int o = gid & 63;
    const float* p = g_pts_sorted + node * 3;
    float a = p[0] * w1[o * 3 + 0] + p[1] * w1[o * 3 + 1] + p[2] * w1[o * 3 + 2];
    float v = fmaxf(a * g1[o] + b1[o], 0.0f);
    bf16 h = __float2bfloat16(v);
    size_t idx = (size_t)node * 64 + o;
    g_xh[idx] = h;
    g_xl[idx] = __float2bfloat16(v - __bfloat162float(h));
}

// ================= HMMA GEMM v3: cp.async pipelined, pre-split bf16 hi/lo =================
// OUT_MODE: 0 = fp32 C, 1 = split bf16 Ch/Cl, 2 = fused channel max-pool into g_pool.
// NSTAGE: smem pipeline stages (1 for K=64 single-chunk, 2 for K>=128).
template <int BN, int OUT_MODE, int NSTAGE>
__global__ void __launch_bounds__(256, 1)
hmma_gemm3(const bf16* __restrict__ Ah, const bf16* __restrict__ Al,
           const bf16* __restrict__ Wh, const bf16* __restrict__ Wl,
           float* __restrict__ C, bf16* __restrict__ Ch, bf16* __restrict__ Cl,
           int M, int N, int K,
           const float* __restrict__ gamma, const float* __restrict__ beta,
           const float* __restrict__ rowscale, int do_relu) {
    extern __shared__ char sm_raw[];
    __shared__ unsigned spool[128];
    uint32_t raw_s = smem_u32(sm_raw);
    uint32_t base_s = (raw_s + 1023u) & ~1023u;
    char* dsm = sm_raw + (base_s - raw_s);

    constexpr int ABYTES = 128 * 64 * 2;
    constexpr int BBYTES = BN * 64 * 2;
    constexpr int STAGE = 2 * ABYTES + 2 * BBYTES;
    constexpr int NI = BN / 32;
    constexpr int WN = BN / 4;

    int tid = threadIdx.x;
    int lane = tid & 31;
    int wid = tid >> 5;
    int wm = wid >> 2;
    int wn = wid & 3;
    int m0 = blockIdx.y * 128;
    int n0 = blockIdx.x * BN;

    if (OUT_MODE == 2 && tid < BN) spool[tid] = 0u;

    auto copy_chunk = [&](int cc, char* st) {
        char* pAh = st;
        char* pAl = pAh + ABYTES;
        char* pBh = pAl + ABYTES;
        char* pBl = pBh + BBYTES;
        int k0g = cc << 6;
        #pragma unroll
        for (int i = 0; i < 4; i++) {
            int g = tid + i * 256;
            int row = g >> 3, kg = g & 7;
            size_t src = (size_t)(m0 + row) * K + k0g + kg * 8;
            uint32_t off = SW128((uint32_t)(row * 128 + kg * 16));
            cp16(smem_u32(pAh + off), Ah + src);
            cp16(smem_u32(pAl + off), Al + src);
        }
        #pragma unroll
        for (int i = 0; i < (BN * 8) / 256; i++) {
            int g = tid + i * 256;
            int row = g >> 3, kg = g & 7;
            size_t src = (size_t)(n0 + row) * K + k0g + kg * 8;
            uint32_t off = SW128((uint32_t)(row * 128 + kg * 16));
            cp16(smem_u32(pBh + off), Wh + src);
            cp16(smem_u32(pBl + off), Wl + src);
        }
    };

    float acc[4][NI][4];
    #pragma unroll
    for (int mi = 0; mi < 4; mi++)
        #pragma unroll
        for (int ni = 0; ni < NI; ni++)
            #pragma unroll
            for (int r = 0; r < 4; r++) acc[mi][ni][r] = 0.0f;

    int nchunks = K >> 6;
    copy_chunk(0, dsm);
    CP_COMMIT();

    for (int c = 0; c < nchunks; c++) {
        char* st = dsm + (c % NSTAGE) * STAGE;
        if (NSTAGE == 1 && c > 0) { copy_chunk(c, st); CP_COMMIT(); }
        CP_WAIT0();
        __syncthreads();
        if (NSTAGE > 1 && c + 1 < nchunks) {
            copy_chunk(c + 1, dsm + ((c + 1) % NSTAGE) * STAGE);
            CP_COMMIT();
        }
        uint32_t sAh = smem_u32(st);
        uint32_t sAl = sAh + ABYTES;
        uint32_t sBh = sAl + ABYTES;
        uint32_t sBl = sBh + BBYTES;

        #pragma unroll
        for (int kk = 0; kk < 4; kk++) {
            int k0 = kk * 16;
            uint32_t aH[4][4], aL[4][4], bH[NI][2], bL[NI][2];
            #pragma unroll
            for (int mi = 0; mi < 4; mi++) {
                int row = wm * 64 + mi * 16 + (lane & 15);
                uint32_t off = SW128((uint32_t)(row * 128 + (k0 + ((lane >> 4) << 3)) * 2));
                ldsm_x4(aH[mi], sAh + off);
                ldsm_x4(aL[mi], sAl + off);
            }
            #pragma unroll
            for (int ni = 0; ni < NI; ni++) {
                int nrow = wn * WN + ni * 8 + (lane & 7);
                uint32_t off = SW128((uint32_t)(nrow * 128 + (k0 + (((lane >> 3) & 1) << 3)) * 2));
                ldsm_x2(bH[ni], sBh + off);
                ldsm_x2(bL[ni], sBl + off);
            }
            #pragma unroll
            for (int mi = 0; mi < 4; mi++)
                #pragma unroll
                for (int ni = 0; ni < NI; ni++) {
                    mma16816(acc[mi][ni], aH[mi], bH[ni]);
                    mma16816(acc[mi][ni], aH[mi], bL[ni]);
                    mma16816(acc[mi][ni], aL[mi], bH[ni]);
                }
        }
        __syncthreads();
    }

    // ---- epilogue ----
    float pmax[NI][2];
    if (OUT_MODE == 2) {
        #pragma unroll
        for (int ni = 0; ni < NI; ni++) { pmax[ni][0] = 0.0f; pmax[ni][1] = 0.0f; }
    }
    #pragma unroll
    for (int mi = 0; mi < 4; mi++) {
        int r0 = m0 + wm * 64 + mi * 16 + (lane >> 2);
        int r1 = r0 + 8;
        float rs0 = rowscale ? rowscale[r0] : 1.0f;
        float rs1 = rowscale ? rowscale[r1] : 1.0f;
        #pragma unroll
        for (int ni = 0; ni < NI; ni++) {
            int cN = n0 + wn * WN + ni * 8 + (lane & 3) * 2;
            float gm0 = 1.0f, gm1 = 1.0f, be0 = 0.0f, be1 = 0.0f;
            if (gamma) { gm0 = gamma[cN]; gm1 = gamma[cN + 1]; be0 = beta[cN]; be1 = beta[cN + 1]; }
            float x0 = acc[mi][ni][0] * rs0 * gm0 + be0;
            float x1 = acc[mi][ni][1] * rs0 * gm1 + be1;
            float x2 = acc[mi][ni][2] * rs1 * gm0 + be0;
            float x3 = acc[mi][ni][3] * rs1 * gm1 + be1;
            if (do_relu) {
                x0 = fmaxf(x0, 0.0f); x1 = fmaxf(x1, 0.0f);
                x2 = fmaxf(x2, 0.0f); x3 = fmaxf(x3, 0.0f);
            }
            if (OUT_MODE == 0) {
                *(float2*)(C + (size_t)r0 * N + cN) = make_float2(x0, x1);
                *(float2*)(C + (size_t)r1 * N + cN) = make_float2(x2, x3);
            } else if (OUT_MODE == 1) {
                uint32_t h01, l01, h23, l23;
                split2(x0, x1, h01, l01);
                split2(x2, x3, h23, l23);
                *(uint32_t*)(Ch + (size_t)r0 * N + cN) = h01;
                *(uint32_t*)(Cl + (size_t)r0 * N + cN) = l01;
                *(uint32_t*)(Ch + (size_t)r1 * N + cN) = h23;
                *(uint32_t*)(Cl + (size_t)r1 * N + cN) = l23;
            } else {
                pmax[ni][0] = fmaxf(pmax[ni][0], fmaxf(x0, x2));
                pmax[ni][1] = fmaxf(pmax[ni][1], fmaxf(x1, x3));
            }
        }
    }
    if (OUT_MODE == 2) {
        #pragma unroll
        for (int ni = 0; ni < NI; ni++) {
            int col = wn * WN + ni * 8 + (lane & 3) * 2;
            atomicMax(&spool[col], __float_as_uint(pmax[ni][0]));
            atomicMax(&spool[col + 1], __float_as_uint(pmax[ni][1]));
        }
        __syncthreads();
        if (tid < BN) atomicMax(&g_pool[n0 + tid], spool[tid]);
    }
}

// ---------------- GCN aggregate: split-output version ----------------
__global__ void agg_kernel(const float* __restrict__ hw, const float* __restrict__ bias,
                           bf16* __restrict__ Ch, bf16* __restrict__ Cl, int F, int do_relu) {
    size_t gid = (size_t)blockIdx.x * blockDim.x + threadIdx.x;
    int node = (int)(gid / F);
    int f = (int)(gid - (size_t)node * F);
    const int* nb = g_nbr + node * KNN;
    float s = hw[(size_t)nb[0] * F + f];
    s += hw[(size_t)nb[1] * F + f];
    s += hw[(size_t)nb[2] * F + f];
    s += hw[(size_t)nb[3] * F + f];
    s += hw[(size_t)nb[4] * F + f];
    float v = s * 0.44721359549995793f + bias[f];   // rsqrt(5) == norm_in (deg_in == 5 always)
    if (do_relu) v = fmaxf(v, 0.0f);
    bf16 h = __float2bfloat16(v);
    Ch[gid] = h;
    Cl[gid] = __float2bfloat16(v - __bfloat162float(h));
}

// ---------------- final linear 256 -> 128 ----------------
__global__ void final_kernel(const float* __restrict__ fc3_w, const float* __restrict__ fc3_b,
                             float* __restrict__ out) {
    int o = threadIdx.x;
    float s = 0.0f;
    #pragma unroll 8
    for (int k = 0; k < 256; k++)
        s += __uint_as_float(g_pool[k]) * fc3_w[o * 256 + k];
    out[o] = s + fc3_b[o];
}

// ---------------- orchestration ----------------
extern "C" void kernel_launch(void* const* d_in, const int* in_sizes, int n_in,
                              void* d_out, int out_size) {
    const float* pts  = (const float*)d_in[0];
    const float* w1   = (const float*)d_in[1];
    const float* g1   = (const float*)d_in[2];
    const float* b1   = (const float*)d_in[3];
    const float* w2   = (const float*)d_in[4];
    const float* g2   = (const float*)d_in[5];
    const float* b2   = (const float*)d_in[6];
    const float* w3   = (const float*)d_in[7];
    const float* g3   = (const float*)d_in[8];
    const float* b3   = (const float*)d_in[9];
    const float* w4   = (const float*)d_in[10];
    const float* g4   = (const float*)d_in[11];
    const float* b4   = (const float*)d_in[12];
    const float* gc1w = (const float*)d_in[13];
    const float* gc1b = (const float*)d_in[14];
    const float* gc2w = (const float*)d_in[15];
    const float* gc2b = (const float*)d_in[16];
    const float* gc3w = (const float*)d_in[17];
    const float* gc3b = (const float*)d_in[18];
    const float* fc1w = (const float*)d_in[19];
    const float* bf1g = (const float*)d_in[20];
    const float* bf1b = (const float*)d_in[21];
    const float* fc2w = (const float*)d_in[22];
    const float* bf2g = (const float*)d_in[23];
    const float* bf2b = (const float*)d_in[24];
    const float* fc3w = (const float*)d_in[25];
    const float* fc3b = (const float*)d_in[26];
    float* out = (float*)d_out;

    void* p;
    cudaGetSymbolAddress(&p, g_bufA);  float* bufA = (float*)p;
    cudaGetSymbolAddress(&p, g_norm);  float* normp = (float*)p;
    cudaGetSymbolAddress(&p, g_xh);    bf16* xh = (bf16*)p;
    cudaGetSymbolAddress(&p, g_xl);    bf16* xl = (bf16*)p;
    cudaGetSymbolAddress(&p, g_yh);    bf16* yh = (bf16*)p;
    cudaGetSymbolAddress(&p, g_yl);    bf16* yl = (bf16*)p;
    cudaGetSymbolAddress(&p, g_wh);    bf16* wh = (bf16*)p;
    cudaGetSymbolAddress(&p, g_wl);    bf16* wl = (bf16*)p;

    const int ST64  = 2 * 128 * 64 * 2 + 2 * 64 * 64 * 2;    // 49152
    const int ST128 = 2 * 128 * 64 * 2 + 2 * 128 * 64 * 2;   // 65536
    const int SM64_1  = ST64 + 1024;
    const int SM128_1 = ST128 + 1024;
    const int SM128_2 = 2 * ST128 + 1024;                     // 132096
    cudaFuncSetAttribute(hmma_gemm3<64, 1, 1>,  cudaFuncAttributeMaxDynamicSharedMemorySize, SM64_1);
    cudaFuncSetAttribute(hmma_gemm3<128, 1, 1>, cudaFuncAttributeMaxDynamicSharedMemorySize, SM128_1);
    cudaFuncSetAttribute(hmma_gemm3<128, 0, 2>, cudaFuncAttributeMaxDynamicSharedMemorySize, SM128_2);
    cudaFuncSetAttribute(hmma_gemm3<128, 1, 2>, cudaFuncAttributeMaxDynamicSharedMemorySize, SM128_2);
    cudaFuncSetAttribute(hmma_gemm3<128, 2, 2>, cudaFuncAttributeMaxDynamicSharedMemorySize, SM128_2);

    const int M = BNODES;

    init_kernel<<<(BNODES + 255) / 256, 256>>>();

    WSegs S;
    S.src[0] = w2;   S.dst[0] = OFF_W2;  S.K[0] = 64;  S.N[0] = 64;  S.trans[0] = 0; S.cnt[0] = 4096;
    S.src[1] = w3;   S.dst[1] = OFF_W3;  S.K[1] = 64;  S.N[1] = 64;  S.trans[1] = 0; S.cnt[1] = 4096;
    S.src[2] = w4;   S.dst[2] = OFF_W4;  S.K[2] = 64;  S.N[2] = 128; S.trans[2] = 0; S.cnt[2] = 8192;
    S.src[3] = gc1w; S.dst[3] = OFF_GC1; S.K[3] = 128; S.N[3] = 128; S.trans[3] = 1; S.cnt[3] = 16384;
    S.src[4] = gc2w; S.dst[4] = OFF_GC2; S.K[4] = 128; S.N[4] = 128; S.trans[4] = 1; S.cnt[4] = 16384;
    S.src[5] = gc3w; S.dst[5] = OFF_GC3; S.K[5] = 128; S.N[5] = 256; S.trans[5] = 1; S.cnt[5] = 32768;
    S.src[6] = fc1w; S.dst[6] = OFF_FC1; S.K[6] = 256; S.N[6] = 512; S.trans[6] = 0; S.cnt[6] = 131072;
    S.src[7] = fc2w; S.dst[7] = OFF_FC2; S.K[7] = 512; S.N[7] = 256; S.trans[7] = 0; S.cnt[7] = 131072;
    wprep_all<<<344064 / 256, 256>>>(S);

    prep_kernel<<<NBATCH, 256>>>(pts);
    sort_warp_kernel<<<dim3(NBATCH, NPTS / 64), 256>>>(pts);
    knn_part_kernel<<<dim3(NBATCH, 16 * NCH), 256>>>(pts);
    knn_merge_kernel<<<BNODES / 256, 256>>>();
    norm_kernel<<<(BNODES + 255) / 256, 256>>>();

    // local conv stack (split-in, split-out)
    layer1_kernel<<<(BNODES * 64) / 256, 256>>>(w1, g1, b1);
    hmma_gemm3<64, 1, 1><<<dim3(1, M / 128), 256, SM64_1>>>(
        xh, xl, wh + OFF_W2, wl + OFF_W2, nullptr, yh, yl, M, 64, 64, g2, b2, nullptr, 1);
    hmma_gemm3<64, 1, 1><<<dim3(1, M / 128), 256, SM64_1>>>(
        yh, yl, wh + OFF_W3, wl + OFF_W3, nullptr, xh, xl, M, 64, 64, g3, b3, nullptr, 1);
    hmma_gemm3<128, 1, 1><<<dim3(1, M / 128), 256, SM128_1>>>(
        xh, xl, wh + OFF_W4, wl + OFF_W4, nullptr, yh, yl, M, 128, 64, g4, b4, nullptr, 1);

    // GCN layers
    hmma_gemm3<128, 0, 2><<<dim3(1, M / 128), 256, SM128_2>>>(
        yh, yl, wh + OFF_GC1, wl + OFF_GC1, bufA, nullptr, nullptr, M, 128, 128, nullptr, nullptr, normp, 0);
    agg_kernel<<<(M * 128) / 256, 256>>>(bufA, gc1b, xh, xl, 128, 1);
    hmma_gemm3<128, 0, 2><<<dim3(1, M / 128), 256, SM128_2>>>(
        xh, xl, wh + OFF_GC2, wl + OFF_GC2, bufA, nullptr, nullptr, M, 128, 128, nullptr, nullptr, normp, 0);
    agg_kernel<<<(M * 128) / 256, 256>>>(bufA, gc2b, yh, yl, 128, 1);
    hmma_gemm3<128, 0, 2><<<dim3(2, M / 128), 256, SM128_2>>>(
        yh, yl, wh + OFF_GC3, wl + OFF_GC3, bufA, nullptr, nullptr, M, 256, 128, nullptr, nullptr, normp, 0);
    agg_kernel<<<(M * 256) / 256, 256>>>(bufA, gc3b, xh, xl, 256, 0);

    // head
    hmma_gemm3<128, 1, 2><<<dim3(4, M / 128), 256, SM128_2>>>(
        xh, xl, wh + OFF_FC1, wl + OFF_FC1, nullptr, yh, yl, M, 512, 256, bf1g, bf1b, nullptr, 1);
    hmma_gemm3<128, 2, 2><<<dim3(2, M / 128), 256, SM128_2>>>(
        yh, yl, wh + OFF_FC2, wl + OFF_FC2, nullptr, nullptr, nullptr, M, 256, 512, bf2g, bf2b, nullptr, 1);

    final_kernel<<<1, 128>>>(fc3w, fc3b, out);
}

// round 15
// speedup vs baseline: 1.0007x; 1.0005x over previous
#include <cuda_runtime.h>
#include <cuda_bf16.h>
#include <cstdint>
#include <cstddef>

#define NPTS 4096
#define NBATCH 8
#define BNODES (NBATCH * NPTS)   // 32768
#define KNN 5
#define NCH 8
#define CHSZ (NPTS / NCH)        // 512

typedef __nv_bfloat16 bf16;

// ---------------- scratch (static device globals; no runtime alloc) ----------------
__device__ __align__(256) float g_pts_sorted[BNODES * 3];
__device__ __align__(256) float g_sq[BNODES];
__device__ __align__(256) float g_dcent[BNODES];
__device__ __align__(256) int   g_nbr[BNODES * KNN];
__device__ __align__(256) int   g_deg[BNODES];
__device__ __align__(256) float g_norm[BNODES];
__device__ __align__(256) float g_kd[(size_t)BNODES * NCH * KNN];
__device__ __align__(256) int   g_kj[(size_t)BNODES * NCH * KNN];
__device__ __align__(256) float g_bufA[(size_t)BNODES * 256];
__device__ __align__(256) bf16  g_xh[(size_t)BNODES * 512];
__device__ __align__(256) bf16  g_xl[(size_t)BNODES * 512];
__device__ __align__(256) bf16  g_yh[(size_t)BNODES * 512];
__device__ __align__(256) bf16  g_yl[(size_t)BNODES * 512];
__device__ __align__(256) bf16  g_wh[344064];
__device__ __align__(256) bf16  g_wl[344064];
__device__ __align__(256) unsigned g_pool[256];

// weight offsets (elements, [N][K] layout)
#define OFF_W2  0
#define OFF_W3  4096
#define OFF_W4  8192
#define OFF_GC1 16384
#define OFF_GC2 32768
#define OFF_GC3 49152
#define OFF_FC1 81920
#define OFF_FC2 212992

// ================= helpers =================
__device__ __forceinline__ uint32_t smem_u32(const void* p) {
    uint32_t a;
    asm("{ .reg .u64 t; cvta.to.shared.u64 t, %1; cvt.u32.u64 %0, t; }" : "=r"(a) : "l"(p));
    return a;
}
#define SW128(off) ((off) ^ (((off) >> 3) & 0x70))

__device__ __forceinline__ void cp16(uint32_t saddr, const void* gptr) {
    asm volatile("cp.async.cg.shared.global [%0], [%1], 16;" :: "r"(saddr), "l"(gptr));
}
#define CP_COMMIT() asm volatile("cp.async.commit_group;" ::: "memory")
#define CP_WAIT0()  asm volatile("cp.async.wait_group 0;" ::: "memory")

__device__ __forceinline__ void ldsm_x4(uint32_t* r, uint32_t addr) {
    asm volatile("ldmatrix.sync.aligned.m8n8.x4.shared.b16 {%0,%1,%2,%3}, [%4];"
                 : "=r"(r[0]), "=r"(r[1]), "=r"(r[2]), "=r"(r[3]) : "r"(addr));
}
__device__ __forceinline__ void ldsm_x2(uint32_t* r, uint32_t addr) {
    asm volatile("ldmatrix.sync.aligned.m8n8.x2.shared.b16 {%0,%1}, [%2];"
                 : "=r"(r[0]), "=r"(r[1]) : "r"(addr));
}
__device__ __forceinline__ void mma16816(float* d, const uint32_t* a, const uint32_t* b) {
    asm volatile(
        "mma.sync.aligned.m16n8k16.row.col.f32.bf16.bf16.f32 "
        "{%0,%1,%2,%3}, {%4,%5,%6,%7}, {%8,%9}, {%0,%1,%2,%3};"
        : "+f"(d[0]), "+f"(d[1]), "+f"(d[2]), "+f"(d[3])
        : "r"(a[0]), "r"(a[1]), "r"(a[2]), "r"(a[3]), "r"(b[0]), "r"(b[1]));
}

__device__ __forceinline__ void split2(float f0, float f1, uint32_t& hi, uint32_t& lo) {
    bf16 h0 = __float2bfloat16(f0), h1 = __float2bfloat16(f1);
    float r0 = f0 - __bfloat162float(h0);
    float r1 = f1 - __bfloat162float(h1);
    bf16 l0 = __float2bfloat16(r0), l1 = __float2bfloat16(r1);
    hi = ((uint32_t)__bfloat16_as_ushort(h1) << 16) | (uint32_t)__bfloat16_as_ushort(h0);
    lo = ((uint32_t)__bfloat16_as_ushort(l1) << 16) | (uint32_t)__bfloat16_as_ushort(l0);
}

// ---------------- init ----------------
__global__ void init_kernel() {
    int i = blockIdx.x * blockDim.x + threadIdx.x;
    if (i < BNODES) g_deg[i] = 0;
    if (i < 256) g_pool[i] = 0u;
}

// ---------------- fused weight pre-split (one launch, 8 segments) ----------------
struct WSegs {
    const float* src[8];
    int dst[8], K[8], N[8], trans[8], cnt[8];
};
__global__ void wprep_all(WSegs S) {
    int o = blockIdx.x * blockDim.x + threadIdx.x;
    #pragma unroll
    for (int s = 0; s < 8; s++) {
        if (o < S.cnt[s]) {
            int K = S.K[s];
            int n = o / K, k = o - n * K;
            float f = S.trans[s] ? S.src[s][k * S.N[s] + n] : S.src[s][o];
            bf16 h = __float2bfloat16(f);
            g_wh[S.dst[s] + o] = h;
            g_wl[S.dst[s] + o] = __float2bfloat16(f - __bfloat162float(h));
            return;
        }
        o -= S.cnt[s];
    }
}

// ---------------- centroid + sq + d_cent ----------------
__global__ void prep_kernel(const float* __restrict__ pts) {
    int b = blockIdx.x;
    int tid = threadIdx.x;
    const float* p = pts + (size_t)b * 3 * NPTS;
    float sx = 0.f, sy = 0.f, sz = 0.f;
    for (int n = tid; n < NPTS; n += 256) {
        sx += p[n];
        sy += p[NPTS + n];
        sz += p[2 * NPTS + n];
    }
    __shared__ float rx[256], ry[256], rz[256];
    rx[tid] = sx; ry[tid] = sy; rz[tid] = sz;
    __syncthreads();
    for (int s = 128; s > 0; s >>= 1) {
        if (tid < s) { rx[tid] += rx[tid + s]; ry[tid] += ry[tid + s]; rz[tid] += rz[tid + s]; }
        __syncthreads();
    }
    __shared__ float cx, cy, cz;
    if (tid == 0) {
        cx = rx[0] / (float)NPTS;
        cy = ry[0] / (float)NPTS;
        cz = rz[0] / (float)NPTS;
    }
    __syncthreads();
    for (int n = tid; n < NPTS; n += 256) {
        float x = p[n], y = p[NPTS + n], z = p[2 * NPTS + n];
        g_sq[b * NPTS + n] = x * x + y * y + z * z;
        float dx = x - cx, dy = y - cy, dz = z - cz;
        g_dcent[b * NPTS + n] = dx * dx + dy * dy + dz * dz;
    }
}

// ---------------- stable argsort by rank counting (warp-cooperative, 8 pts/warp) ----------------
__global__ void sort_warp_kernel(const float* __restrict__ pts) {
    __shared__ float sd[NPTS];
    int b = blockIdx.x;
    int tid = threadIdx.x;
    for (int j = tid; j < NPTS; j += 256) sd[j] = g_dcent[b * NPTS + j];
    __syncthreads();
    int wid = tid >> 5, lane = tid & 31;
    int i_base = (blockIdx.y * 8 + wid) * 8;
    float di[8];
    int rank[8];
    #pragma unroll
    for (int q = 0; q < 8; q++) { di[q] = sd[i_base + q]; rank[q] = 0; }
    #pragma unroll 4
    for (int t = 0; t < 128; t++) {
        int j = lane + t * 32;
        float dj = sd[j];
        #pragma unroll
        for (int q = 0; q < 8; q++)
            rank[q] += (dj < di[q]) || (dj == di[q] && j < i_base + q);
    }
    #pragma unroll
    for (int q = 0; q < 8; q++) {
        #pragma unroll
        for (int off = 16; off; off >>= 1)
            rank[q] += __shfl_xor_sync(0xffffffffu, rank[q], off);
    }
    const float* p = pts + (size_t)b * 3 * NPTS;
    #pragma unroll
    for (int q = 0; q < 8; q++) {
        if (lane == q) {
            int i = i_base + q;
            int dst = (b * NPTS + rank[q]) * 3;
            g_pts_sorted[dst + 0] = p[i];
            g_pts_sorted[dst + 1] = p[NPTS + i];
            g_pts_sorted[dst + 2] = p[2 * NPTS + i];
        }
    }
}

// ---------------- KNN pass 1: per-(query, chunk) top-5 over 512 candidates ----------------
__global__ void knn_part_kernel(const float* __restrict__ pts) {
    __shared__ float4 cs[CHSZ];
    int b = blockIdx.x;
    int c = blockIdx.y >> 4;
    int qblk = blockIdx.y & 15;
    int tid = threadIdx.x;
    const float* p = pts + (size_t)b * 3 * NPTS;
    for (int j = tid; j < CHSZ; j += 256) {
        int jj = c * CHSZ + j;
        cs[j] = make_float4(p[jj], p[NPTS + jj], p[2 * NPTS + jj], g_sq[b * NPTS + jj]);
    }
    __syncthreads();
    int i = qblk * 256 + tid;
    float sqi = g_sq[b * NPTS + i];
    float qx = -2.0f * p[i], qy = -2.0f * p[NPTS + i], qz = -2.0f * p[2 * NPTS + i];

    float bd0 = 3.0e38f, bd1 = 3.0e38f, bd2 = 3.0e38f, bd3 = 3.0e38f, bd4 = 3.0e38f;
    int bj0 = 0x7fffffff, bj1 = 0x7fffffff, bj2 = 0x7fffffff, bj3 = 0x7fffffff, bj4 = 0x7fffffff;

    #pragma unroll 8
    for (int j = 0; j < CHSZ; j++) {
        float4 cj = cs[j];
        float d = fmaf(qx, cj.x, fmaf(qy, cj.y, fmaf(qz, cj.z, cj.w))) + sqi;
        if (d < bd4) {                      // strict <: earlier j wins ties (matches top_k)
            int jj = c * CHSZ + j;
            if (d < bd0) {
                bd4 = bd3; bj4 = bj3; bd3 = bd2; bj3 = bj2; bd2 = bd1; bj2 = bj1;
                bd1 = bd0; bj1 = bj0; bd0 = d; bj0 = jj;
            } else if (d < bd1) {
                bd4 = bd3; bj4 = bj3; bd3 = bd2; bj3 = bj2; bd2 = bd1; bj2 = bj1;
                bd1 = d; bj1 = jj;
            } else if (d < bd2) {
                bd4 = bd3; bj4 = bj3; bd3 = bd2; bj3 = bj2; bd2 = d; bj2 = jj;
            } else if (d < bd3) {
                bd4 = bd3; bj4 = bj3; bd3 = d; bj3 = jj;
            } else {
                bd4 = d; bj4 = jj;
            }
        }
    }
    size_t base = ((size_t)(b * NPTS + i) * NCH + c) * KNN;
    g_kd[base + 0] = bd0; g_kd[base + 1] = bd1; g_kd[base + 2] = bd2;
    g_kd[base + 3] = bd3; g_kd[base + 4] = bd4;
    g_kj[base + 0] = bj0; g_kj[base + 1] = bj1; g_kj[base + 2] = bj2;
    g_kj[base + 3] = bj3; g_kj[base + 4] = bj4;
}

// ---------------- KNN pass 2: merge 8 sorted 5-lists -> global top-5; count deg ----------------
__global__ void knn_merge_kernel() {
    int node = blockIdx.x * blockDim.x + threadIdx.x;
    int b = node >> 12;
    size_t base = (size_t)node * NCH * KNN;
    float hd[NCH];
    int hj[NCH], hp[NCH];
    #pragma unroll
    for (int c = 0; c < NCH; c++) {
        hd[c] = g_kd[base + c * KNN];
        hj[c] = g_kj[base + c * KNN];
        hp[c] = 0;
    }
    int out_base = node * KNN;
    int off = b * NPTS;
    #pragma unroll
    for (int r = 0; r < KNN; r++) {
        int best = 0;
        float d = hd[0];
        int j = hj[0];
        #pragma unroll
        for (int c = 1; c < NCH; c++) {
            if (hd[c] < d || (hd[c] == d && hj[c] < j)) { d = hd[c]; j = hj[c]; best = c; }
        }
        int nj = off + j;
        g_nbr[out_base + r] = nj;
        atomicAdd(&g_deg[nj], 1);
        int np = ++hp[best];
        if (np < KNN) {
            hd[best] = g_kd[base + best * KNN + np];
            hj[best] = g_kj[base + best * KNN + np];
        } else {
            hd[best] = 3.0e38f;
            hj[best] = 0x7fffffff;
        }
    }
}

__global__ void norm_kernel() {
    int i = blockIdx.x * blockDim.x + threadIdx.x;
    if (i < BNODES) g_norm[i] = rsqrtf(fmaxf((float)g_deg[i], 1.0f));
}

// ---------------- layer 1: 3 -> 64 pointwise + BN-affine + ReLU, split output ----------------
__global__ void layer1_kernel(const float* __restrict__ w1, const float* __restrict__ g1,
                              const float* __restrict__ b1) {
    int gid = blockIdx.x * blockDim.x + threadIdx.x;
    int node = gid >> 6;
    int o = gid & 63;
    const float* p = g_pts_sorted + node * 3;
    float a = p[0] * w1[o * 3 + 0] + p[1] * w1[o * 3 + 1] + p[2] * w1[o * 3 + 2];
    float v = fmaxf(a * g1[o] + b1[o], 0.0f);
    bf16 h = __float2bfloat16(v);
    size_t idx = (size_t)node * 64 + o;
    g_xh[idx] = h;
    g_xl[idx] = __float2bfloat16(v - __bfloat162float(h));
}

// ================= HMMA GEMM v3: cp.async pipelined, pre-split bf16 hi/lo =================
// OUT_MODE: 0 = fp32 C, 1 = split bf16 Ch/Cl, 2 = fused channel max-pool into g_pool.
// NSTAGE: smem pipeline stages (1 for K=64 single-chunk, 2 for K>=128).
template <int BN, int OUT_MODE, int NSTAGE>
__global__ void __launch_bounds__(256, 1)
hmma_gemm3(const bf16* __restrict__ Ah, const bf16* __restrict__ Al,
           const bf16* __restrict__ Wh, const bf16* __restrict__ Wl,
           float* __restrict__ C, bf16* __restrict__ Ch, bf16* __restrict__ Cl,
           int M, int N, int K,
           const float* __restrict__ gamma, const float* __restrict__ beta,
           const float* __restrict__ rowscale, int do_relu) {
    extern __shared__ char sm_raw[];
    __shared__ unsigned spool[128];
    uint32_t raw_s = smem_u32(sm_raw);
    uint32_t base_s = (raw_s + 1023u) & ~1023u;
    char* dsm = sm_raw + (base_s - raw_s);

    constexpr int ABYTES = 128 * 64 * 2;
    constexpr int BBYTES = BN * 64 * 2;
    constexpr int STAGE = 2 * ABYTES + 2 * BBYTES;
    constexpr int NI = BN / 32;
    constexpr int WN = BN / 4;

    int tid = threadIdx.x;
    int lane = tid & 31;
    int wid = tid >> 5;
    int wm = wid >> 2;
    int wn = wid & 3;
    int m0 = blockIdx.y * 128;
    int n0 = blockIdx.x * BN;

    if (OUT_MODE == 2 && tid < BN) spool[tid] = 0u;

    auto copy_chunk = [&](int cc, char* st) {
        char* pAh = st;
        char* pAl = pAh + ABYTES;
        char* pBh = pAl + ABYTES;
        char* pBl = pBh + BBYTES;
        int k0g = cc << 6;
        #pragma unroll
        for (int i = 0; i < 4; i++) {
            int g = tid + i * 256;
            int row = g >> 3, kg = g & 7;
            size_t src = (size_t)(m0 + row) * K + k0g + kg * 8;
            uint32_t off = SW128((uint32_t)(row * 128 + kg * 16));
            cp16(smem_u32(pAh + off), Ah + src);
            cp16(smem_u32(pAl + off), Al + src);
        }
        #pragma unroll
        for (int i = 0; i < (BN * 8) / 256; i++) {
            int g = tid + i * 256;
            int row = g >> 3, kg = g & 7;
            size_t src = (size_t)(n0 + row) * K + k0g + kg * 8;
            uint32_t off = SW128((uint32_t)(row * 128 + kg * 16));
            cp16(smem_u32(pBh + off), Wh + src);
            cp16(smem_u32(pBl + off), Wl + src);
        }
    };

    float acc[4][NI][4];
    #pragma unroll
    for (int mi = 0; mi < 4; mi++)
        #pragma unroll
        for (int ni = 0; ni < NI; ni++)
            #pragma unroll
            for (int r = 0; r < 4; r++) acc[mi][ni][r] = 0.0f;

    int nchunks = K >> 6;
    copy_chunk(0, dsm);
    CP_COMMIT();

    for (int c = 0; c < nchunks; c++) {
        char* st = dsm + (c % NSTAGE) * STAGE;
        if (NSTAGE == 1 && c > 0) { copy_chunk(c, st); CP_COMMIT(); }
        CP_WAIT0();
        __syncthreads();
        if (NSTAGE > 1 && c + 1 < nchunks) {
            copy_chunk(c + 1, dsm + ((c + 1) % NSTAGE) * STAGE);
            CP_COMMIT();
        }
        uint32_t sAh = smem_u32(st);
        uint32_t sAl = sAh + ABYTES;
        uint32_t sBh = sAl + ABYTES;
        uint32_t sBl = sBh + BBYTES;

        #pragma unroll
        for (int kk = 0; kk < 4; kk++) {
            int k0 = kk * 16;
            uint32_t aH[4][4], aL[4][4], bH[NI][2], bL[NI][2];
            #pragma unroll
            for (int mi = 0; mi < 4; mi++) {
                int row = wm * 64 + mi * 16 + (lane & 15);
                uint32_t off = SW128((uint32_t)(row * 128 + (k0 + ((lane >> 4) << 3)) * 2));
                ldsm_x4(aH[mi], sAh + off);
                ldsm_x4(aL[mi], sAl + off);
            }
            #pragma unroll
            for (int ni = 0; ni < NI; ni++) {
                int nrow = wn * WN + ni * 8 + (lane & 7);
                uint32_t off = SW128((uint32_t)(nrow * 128 + (k0 + (((lane >> 3) & 1) << 3)) * 2));
                ldsm_x2(bH[ni], sBh + off);
                ldsm_x2(bL[ni], sBl + off);
            }
            #pragma unroll
            for (int mi = 0; mi < 4; mi++)
                #pragma unroll
                for (int ni = 0; ni < NI; ni++) {
                    mma16816(acc[mi][ni], aH[mi], bH[ni]);
                    mma16816(acc[mi][ni], aH[mi], bL[ni]);
                    mma16816(acc[mi][ni], aL[mi], bH[ni]);
                }
        }
        __syncthreads();
    }

    // ---- epilogue ----
    float pmax[NI][2];
    if (OUT_MODE == 2) {
        #pragma unroll
        for (int ni = 0; ni < NI; ni++) { pmax[ni][0] = 0.0f; pmax[ni][1] = 0.0f; }
    }
    #pragma unroll
    for (int mi = 0; mi < 4; mi++) {
        int r0 = m0 + wm * 64 + mi * 16 + (lane >> 2);
        int r1 = r0 + 8;
        float rs0 = rowscale ? rowscale[r0] : 1.0f;
        float rs1 = rowscale ? rowscale[r1] : 1.0f;
        #pragma unroll
        for (int ni = 0; ni < NI; ni++) {
            int cN = n0 + wn * WN + ni * 8 + (lane & 3) * 2;
            float gm0 = 1.0f, gm1 = 1.0f, be0 = 0.0f, be1 = 0.0f;
            if (gamma) { gm0 = gamma[cN]; gm1 = gamma[cN + 1]; be0 = beta[cN]; be1 = beta[cN + 1]; }
            float x0 = acc[mi][ni][0] * rs0 * gm0 + be0;
            float x1 = acc[mi][ni][1] * rs0 * gm1 + be1;
            float x2 = acc[mi][ni][2] * rs1 * gm0 + be0;
            float x3 = acc[mi][ni][3] * rs1 * gm1 + be1;
            if (do_relu) {
                x0 = fmaxf(x0, 0.0f); x1 = fmaxf(x1, 0.0f);
                x2 = fmaxf(x2, 0.0f); x3 = fmaxf(x3, 0.0f);
            }
            if (OUT_MODE == 0) {
                *(float2*)(C + (size_t)r0 * N + cN) = make_float2(x0, x1);
                *(float2*)(C + (size_t)r1 * N + cN) = make_float2(x2, x3);
            } else if (OUT_MODE == 1) {
                uint32_t h01, l01, h23, l23;
                split2(x0, x1, h01, l01);
                split2(x2, x3, h23, l23);
                *(uint32_t*)(Ch + (size_t)r0 * N + cN) = h01;
                *(uint32_t*)(Cl + (size_t)r0 * N + cN) = l01;
                *(uint32_t*)(Ch + (size_t)r1 * N + cN) = h23;
                *(uint32_t*)(Cl + (size_t)r1 * N + cN) = l23;
            } else {
                pmax[ni][0] = fmaxf(pmax[ni][0], fmaxf(x0, x2));
                pmax[ni][1] = fmaxf(pmax[ni][1], fmaxf(x1, x3));
            }
        }
    }
    if (OUT_MODE == 2) {
        #pragma unroll
        for (int ni = 0; ni < NI; ni++) {
            int col = wn * WN + ni * 8 + (lane & 3) * 2;
            atomicMax(&spool[col], __float_as_uint(pmax[ni][0]));
            atomicMax(&spool[col + 1], __float_as_uint(pmax[ni][1]));
        }
        __syncthreads();
        if (tid < BN) atomicMax(&g_pool[n0 + tid], spool[tid]);
    }
}

// ---------------- GCN aggregate: split-output version ----------------
__global__ void agg_kernel(const float* __restrict__ hw, const float* __restrict__ bias,
                           bf16* __restrict__ Ch, bf16* __restrict__ Cl, int F, int do_relu) {
    size_t gid = (size_t)blockIdx.x * blockDim.x + threadIdx.x;
    int node = (int)(gid / F);
    int f = (int)(gid - (size_t)node * F);
    const int* nb = g_nbr + node * KNN;
    float s = hw[(size_t)nb[0] * F + f];
    s += hw[(size_t)nb[1] * F + f];
    s += hw[(size_t)nb[2] * F + f];
    s += hw[(size_t)nb[3] * F + f];
    s += hw[(size_t)nb[4] * F + f];
    float v = s * 0.44721359549995793f + bias[f];   // rsqrt(5) == norm_in (deg_in == 5 always)
    if (do_relu) v = fmaxf(v, 0.0f);
    bf16 h = __float2bfloat16(v);
    Ch[gid] = h;
    Cl[gid] = __float2bfloat16(v - __bfloat162float(h));
}

// ---------------- final linear 256 -> 128 ----------------
__global__ void final_kernel(const float* __restrict__ fc3_w, const float* __restrict__ fc3_b,
                             float* __restrict__ out) {
    int o = threadIdx.x;
    float s = 0.0f;
    #pragma unroll 8
    for (int k = 0; k < 256; k++)
        s += __uint_as_float(g_pool[k]) * fc3_w[o * 256 + k];
    out[o] = s + fc3_b[o];
}

// ---------------- orchestration ----------------
extern "C" void kernel_launch(void* const* d_in, const int* in_sizes, int n_in,
                              void* d_out, int out_size) {
    const float* pts  = (const float*)d_in[0];
    const float* w1   = (const float*)d_in[1];
    const float* g1   = (const float*)d_in[2];
    const float* b1   = (const float*)d_in[3];
    const float* w2   = (const float*)d_in[4];
    const float* g2   = (const float*)d_in[5];
    const float* b2   = (const float*)d_in[6];
    const float* w3   = (const float*)d_in[7];
    const float* g3   = (const float*)d_in[8];
    const float* b3   = (const float*)d_in[9];
    const float* w4   = (const float*)d_in[10];
    const float* g4   = (const float*)d_in[11];
    const float* b4   = (const float*)d_in[12];
    const float* gc1w = (const float*)d_in[13];
    const float* gc1b = (const float*)d_in[14];
    const float* gc2w = (const float*)d_in[15];
    const float* gc2b = (const float*)d_in[16];
    const float* gc3w = (const float*)d_in[17];
    const float* gc3b = (const float*)d_in[18];
    const float* fc1w = (const float*)d_in[19];
    const float* bf1g = (const float*)d_in[20];
    const float* bf1b = (const float*)d_in[21];
    const float* fc2w = (const float*)d_in[22];
    const float* bf2g = (const float*)d_in[23];
    const float* bf2b = (const float*)d_in[24];
    const float* fc3w = (const float*)d_in[25];
    const float* fc3b = (const float*)d_in[26];
    float* out = (float*)d_out;

    void* p;
    cudaGetSymbolAddress(&p, g_bufA);  float* bufA = (float*)p;
    cudaGetSymbolAddress(&p, g_norm);  float* normp = (float*)p;
    cudaGetSymbolAddress(&p, g_xh);    bf16* xh = (bf16*)p;
    cudaGetSymbolAddress(&p, g_xl);    bf16* xl = (bf16*)p;
    cudaGetSymbolAddress(&p, g_yh);    bf16* yh = (bf16*)p;
    cudaGetSymbolAddress(&p, g_yl);    bf16* yl = (bf16*)p;
    cudaGetSymbolAddress(&p, g_wh);    bf16* wh = (bf16*)p;
    cudaGetSymbolAddress(&p, g_wl);    bf16* wl = (bf16*)p;

    const int ST64  = 2 * 128 * 64 * 2 + 2 * 64 * 64 * 2;    // 49152
    const int ST128 = 2 * 128 * 64 * 2 + 2 * 128 * 64 * 2;   // 65536
    const int SM64_1  = ST64 + 1024;
    const int SM128_1 = ST128 + 1024;
    const int SM128_2 = 2 * ST128 + 1024;                     // 132096
    cudaFuncSetAttribute(hmma_gemm3<64, 1, 1>,  cudaFuncAttributeMaxDynamicSharedMemorySize, SM64_1);
    cudaFuncSetAttribute(hmma_gemm3<128, 1, 1>, cudaFuncAttributeMaxDynamicSharedMemorySize, SM128_1);
    cudaFuncSetAttribute(hmma_gemm3<128, 0, 2>, cudaFuncAttributeMaxDynamicSharedMemorySize, SM128_2);
    cudaFuncSetAttribute(hmma_gemm3<128, 1, 2>, cudaFuncAttributeMaxDynamicSharedMemorySize, SM128_2);
    cudaFuncSetAttribute(hmma_gemm3<128, 2, 2>, cudaFuncAttributeMaxDynamicSharedMemorySize, SM128_2);

    const int M = BNODES;

    init_kernel<<<(BNODES + 255) / 256, 256>>>();

    WSegs S;
    S.src[0] = w2;   S.dst[0] = OFF_W2;  S.K[0] = 64;  S.N[0] = 64;  S.trans[0] = 0; S.cnt[0] = 4096;
    S.src[1] = w3;   S.dst[1] = OFF_W3;  S.K[1] = 64;  S.N[1] = 64;  S.trans[1] = 0; S.cnt[1] = 4096;
    S.src[2] = w4;   S.dst[2] = OFF_W4;  S.K[2] = 64;  S.N[2] = 128; S.trans[2] = 0; S.cnt[2] = 8192;
    S.src[3] = gc1w; S.dst[3] = OFF_GC1; S.K[3] = 128; S.N[3] = 128; S.trans[3] = 1; S.cnt[3] = 16384;
    S.src[4] = gc2w; S.dst[4] = OFF_GC2; S.K[4] = 128; S.N[4] = 128; S.trans[4] = 1; S.cnt[4] = 16384;
    S.src[5] = gc3w; S.dst[5] = OFF_GC3; S.K[5] = 128; S.N[5] = 256; S.trans[5] = 1; S.cnt[5] = 32768;
    S.src[6] = fc1w; S.dst[6] = OFF_FC1; S.K[6] = 256; S.N[6] = 512; S.trans[6] = 0; S.cnt[6] = 131072;
    S.src[7] = fc2w; S.dst[7] = OFF_FC2; S.K[7] = 512; S.N[7] = 256; S.trans[7] = 0; S.cnt[7] = 131072;
    wprep_all<<<344064 / 256, 256>>>(S);

    prep_kernel<<<NBATCH, 256>>>(pts);
    sort_warp_kernel<<<dim3(NBATCH, NPTS / 64), 256>>>(pts);
    knn_part_kernel<<<dim3(NBATCH, 16 * NCH), 256>>>(pts);
    knn_merge_kernel<<<BNODES / 256, 256>>>();
    norm_kernel<<<(BNODES + 255) / 256, 256>>>();

    // local conv stack (split-in, split-out)
    layer1_kernel<<<(BNODES * 64) / 256, 256>>>(w1, g1, b1);
    hmma_gemm3<64, 1, 1><<<dim3(1, M / 128), 256, SM64_1>>>(
        xh, xl, wh + OFF_W2, wl + OFF_W2, nullptr, yh, yl, M, 64, 64, g2, b2, nullptr, 1);
    hmma_gemm3<64, 1, 1><<<dim3(1, M / 128), 256, SM64_1>>>(
        yh, yl, wh + OFF_W3, wl + OFF_W3, nullptr, xh, xl, M, 64, 64, g3, b3, nullptr, 1);
    hmma_gemm3<128, 1, 1><<<dim3(1, M / 128), 256, SM128_1>>>(
        xh, xl, wh + OFF_W4, wl + OFF_W4, nullptr, yh, yl, M, 128, 64, g4, b4, nullptr, 1);

    // GCN layers
    hmma_gemm3<128, 0, 2><<<dim3(1, M / 128), 256, SM128_2>>>(
        yh, yl, wh + OFF_GC1, wl + OFF_GC1, bufA, nullptr, nullptr, M, 128, 128, nullptr, nullptr, normp, 0);
    agg_kernel<<<(M * 128) / 256, 256>>>(bufA, gc1b, xh, xl, 128, 1);
    hmma_gemm3<128, 0, 2><<<dim3(1, M / 128), 256, SM128_2>>>(
        xh, xl, wh + OFF_GC2, wl + OFF_GC2, bufA, nullptr, nullptr, M, 128, 128, nullptr, nullptr, normp, 0);
    agg_kernel<<<(M * 128) / 256, 256>>>(bufA, gc2b, yh, yl, 128, 1);
    hmma_gemm3<128, 0, 2><<<dim3(2, M / 128), 256, SM128_2>>>(
        yh, yl, wh + OFF_GC3, wl + OFF_GC3, bufA, nullptr, nullptr, M, 256, 128, nullptr, nullptr, normp, 0);
    agg_kernel<<<(M * 256) / 256, 256>>>(bufA, gc3b, xh, xl, 256, 0);

    // head
    hmma_gemm3<128, 1, 2><<<dim3(4, M / 128), 256, SM128_2>>>(
        xh, xl, wh + OFF_FC1, wl + OFF_FC1, nullptr, yh, yl, M, 512, 256, bf1g, bf1b, nullptr, 1);
    hmma_gemm3<128, 2, 2><<<dim3(2, M / 128), 256, SM128_2>>>(
        yh, yl, wh + OFF_FC2, wl + OFF_FC2, nullptr, nullptr, nullptr, M, 256, 512, bf2g, bf2b, nullptr, 1);

    final_kernel<<<1, 128>>>(fc3w, fc3b, out);
}

// round 16
// speedup vs baseline: 1.0008x; 1.0001x over previous
#include <cuda_runtime.h>
#include <cuda_bf16.h>
#include <cstdint>
#include <cstddef>

#define NPTS 4096
#define NBATCH 8
#define BNODES (NBATCH * NPTS)   // 32768
#define KNN 5
#define NCH 8
#define CHSZ (NPTS / NCH)        // 512

typedef __nv_bfloat16 bf16;

// ---------------- scratch (static device globals; no runtime alloc) ----------------
__device__ __align__(256) float g_pts_sorted[BNODES * 3];
__device__ __align__(256) float g_sq[BNODES];
__device__ __align__(256) float g_dcent[BNODES];
__device__ __align__(256) int   g_nbr[BNODES * KNN];
__device__ __align__(256) int   g_deg[BNODES];
__device__ __align__(256) float g_norm[BNODES];
__device__ __align__(256) float g_kd[(size_t)BNODES * NCH * KNN];
__device__ __align__(256) int   g_kj[(size_t)BNODES * NCH * KNN];
__device__ __align__(256) float g_bufA[(size_t)BNODES * 256];
__device__ __align__(256) bf16  g_xh[(size_t)BNODES * 512];
__device__ __align__(256) bf16  g_xl[(size_t)BNODES * 512];
__device__ __align__(256) bf16  g_yh[(size_t)BNODES * 512];
__device__ __align__(256) bf16  g_yl[(size_t)BNODES * 512];
__device__ __align__(256) bf16  g_wh[344064];
__device__ __align__(256) bf16  g_wl[344064];
__device__ __align__(256) unsigned g_pool[256];

// weight offsets (elements, [N][K] layout)
#define OFF_W2  0
#define OFF_W3  4096
#define OFF_W4  8192
#define OFF_GC1 16384
#define OFF_GC2 32768
#define OFF_GC3 49152
#define OFF_FC1 81920
#define OFF_FC2 212992

// ================= helpers =================
__device__ __forceinline__ uint32_t smem_u32(const void* p) {
    uint32_t a;
    asm("{ .reg .u64 t; cvta.to.shared.u64 t, %1; cvt.u32.u64 %0, t; }" : "=r"(a) : "l"(p));
    return a;
}
#define SW128(off) ((off) ^ (((off) >> 3) & 0x70))

__device__ __forceinline__ void cp16(uint32_t saddr, const void* gptr) {
    asm volatile("cp.async.cg.shared.global [%0], [%1], 16;" :: "r"(saddr), "l"(gptr));
}
#define CP_COMMIT() asm volatile("cp.async.commit_group;" ::: "memory")
#define CP_WAIT0()  asm volatile("cp.async.wait_group 0;" ::: "memory")

__device__ __forceinline__ void ldsm_x4(uint32_t* r, uint32_t addr) {
    asm volatile("ldmatrix.sync.aligned.m8n8.x4.shared.b16 {%0,%1,%2,%3}, [%4];"
                 : "=r"(r[0]), "=r"(r[1]), "=r"(r[2]), "=r"(r[3]) : "r"(addr));
}
__device__ __forceinline__ void ldsm_x2(uint32_t* r, uint32_t addr) {
    asm volatile("ldmatrix.sync.aligned.m8n8.x2.shared.b16 {%0,%1}, [%2];"
                 : "=r"(r[0]), "=r"(r[1]) : "r"(addr));
}
__device__ __forceinline__ void mma16816(float* d, const uint32_t* a, const uint32_t* b) {
    asm volatile(
        "mma.sync.aligned.m16n8k16.row.col.f32.bf16.bf16.f32 "
        "{%0,%1,%2,%3}, {%4,%5,%6,%7}, {%8,%9}, {%0,%1,%2,%3};"
        : "+f"(d[0]), "+f"(d[1]), "+f"(d[2]), "+f"(d[3])
        : "r"(a[0]), "r"(a[1]), "r"(a[2]), "r"(a[3]), "r"(b[0]), "r"(b[1]));
}

__device__ __forceinline__ void split2(float f0, float f1, uint32_t& hi, uint32_t& lo) {
    bf16 h0 = __float2bfloat16(f0), h1 = __float2bfloat16(f1);
    float r0 = f0 - __bfloat162float(h0);
    float r1 = f1 - __bfloat162float(h1);
    bf16 l0 = __float2bfloat16(r0), l1 = __float2bfloat16(r1);
    hi = ((uint32_t)__bfloat16_as_ushort(h1) << 16) | (uint32_t)__bfloat16_as_ushort(h0);
    lo = ((uint32_t)__bfloat16_as_ushort(l1) << 16) | (uint32_t)__bfloat16_as_ushort(l0);
}

// ---------------- init ----------------
__global__ void init_kernel() {
    int i = blockIdx.x * blockDim.x + threadIdx.x;
    if (i < BNODES) g_deg[i] = 0;
    if (i < 256) g_pool[i] = 0u;
}

// ---------------- fused weight pre-split (one launch, 8 segments) ----------------
struct WSegs {
    const float* src[8];
    int dst[8], K[8], N[8], trans[8], cnt[8];
};
__global__ void wprep_all(WSegs S) {
    int o = blockIdx.x * blockDim.x + threadIdx.x;
    #pragma unroll
    for (int s = 0; s < 8; s++) {
        if (o < S.cnt[s]) {
            int K = S.K[s];
            int n = o / K, k = o - n * K;
            float f = S.trans[s] ? S.src[s][k * S.N[s] + n] : S.src[s][o];
            bf16 h = __float2bfloat16(f);
            g_wh[S.dst[s] + o] = h;
            g_wl[S.dst[s] + o] = __float2bfloat16(f - __bfloat162float(h));
            return;
        }
        o -= S.cnt[s];
    }
}

// ---------------- centroid + sq + d_cent ----------------
__global__ void prep_kernel(const float* __restrict__ pts) {
    int b = blockIdx.x;
    int tid = threadIdx.x;
    const float* p = pts + (size_t)b * 3 * NPTS;
    float sx = 0.f, sy = 0.f, sz = 0.f;
    for (int n = tid; n < NPTS; n += 256) {
        sx += p[n];
        sy += p[NPTS + n];
        sz += p[2 * NPTS + n];
    }
    __shared__ float rx[256], ry[256], rz[256];
    rx[tid] = sx; ry[tid] = sy; rz[tid] = sz;
    __syncthreads();
    for (int s = 128; s > 0; s >>= 1) {
        if (tid < s) { rx[tid] += rx[tid + s]; ry[tid] += ry[tid + s]; rz[tid] += rz[tid + s]; }
        __syncthreads();
    }
    __shared__ float cx, cy, cz;
    if (tid == 0) {
        cx = rx[0] / (float)NPTS;
        cy = ry[0] / (float)NPTS;
        cz = rz[0] / (float)NPTS;
    }
    __syncthreads();
    for (int n = tid; n < NPTS; n += 256) {
        float x = p[n], y = p[NPTS + n], z = p[2 * NPTS + n];
        g_sq[b * NPTS + n] = x * x + y * y + z * z;
        float dx = x - cx, dy = y - cy, dz = z - cz;
        g_dcent[b * NPTS + n] = dx * dx + dy * dy + dz * dz;
    }
}

// ---------------- stable argsort by rank counting (warp-cooperative, 8 pts/warp) ----------------
__global__ void sort_warp_kernel(const float* __restrict__ pts) {
    __shared__ float sd[NPTS];
    int b = blockIdx.x;
    int tid = threadIdx.x;
    for (int j = tid; j < NPTS; j += 256) sd[j] = g_dcent[b * NPTS + j];
    __syncthreads();
    int wid = tid >> 5, lane = tid & 31;
    int i_base = (blockIdx.y * 8 + wid) * 8;
    float di[8];
    int rank[8];
    #pragma unroll
    for (int q = 0; q < 8; q++) { di[q] = sd[i_base + q]; rank[q] = 0; }
    #pragma unroll 4
    for (int t = 0; t < 128; t++) {
        int j = lane + t * 32;
        float dj = sd[j];
        #pragma unroll
        for (int q = 0; q < 8; q++)
            rank[q] += (dj < di[q]) || (dj == di[q] && j < i_base + q);
    }
    #pragma unroll
    for (int q = 0; q < 8; q++) {
        #pragma unroll
        for (int off = 16; off; off >>= 1)
            rank[q] += __shfl_xor_sync(0xffffffffu, rank[q], off);
    }
    const float* p = pts + (size_t)b * 3 * NPTS;
    #pragma unroll
    for (int q = 0; q < 8; q++) {
        if (lane == q) {
            int i = i_base + q;
            int dst = (b * NPTS + rank[q]) * 3;
            g_pts_sorted[dst + 0] = p[i];
            g_pts_sorted[dst + 1] = p[NPTS + i];
            g_pts_sorted[dst + 2] = p[2 * NPTS + i];
        }
    }
}

// ---------------- KNN pass 1: per-(query, chunk) top-5 over 512 candidates ----------------
__global__ void knn_part_kernel(const float* __restrict__ pts) {
    __shared__ float4 cs[CHSZ];
    int b = blockIdx.x;
    int c = blockIdx.y >> 4;
    int qblk = blockIdx.y & 15;
    int tid = threadIdx.x;
    const float* p = pts + (size_t)b * 3 * NPTS;
    for (int j = tid; j < CHSZ; j += 256) {
        int jj = c * CHSZ + j;
        cs[j] = make_float4(p[jj], p[NPTS + jj], p[2 * NPTS + jj], g_sq[b * NPTS + jj]);
    }
    __syncthreads();
    int i = qblk * 256 + tid;
    float sqi = g_sq[b * NPTS + i];
    float qx = -2.0f * p[i], qy = -2.0f * p[NPTS + i], qz = -2.0f * p[2 * NPTS + i];

    float bd0 = 3.0e38f, bd1 = 3.0e38f, bd2 = 3.0e38f, bd3 = 3.0e38f, bd4 = 3.0e38f;
    int bj0 = 0x7fffffff, bj1 = 0x7fffffff, bj2 = 0x7fffffff, bj3 = 0x7fffffff, bj4 = 0x7fffffff;

    #pragma unroll 8
    for (int j = 0; j < CHSZ; j++) {
        float4 cj = cs[j];
        float d = fmaf(qx, cj.x, fmaf(qy, cj.y, fmaf(qz, cj.z, cj.w))) + sqi;
        if (d < bd4) {                      // strict <: earlier j wins ties (matches top_k)
            int jj = c * CHSZ + j;
            if (d < bd0) {
                bd4 = bd3; bj4 = bj3; bd3 = bd2; bj3 = bj2; bd2 = bd1; bj2 = bj1;
                bd1 = bd0; bj1 = bj0; bd0 = d; bj0 = jj;
            } else if (d < bd1) {
                bd4 = bd3; bj4 = bj3; bd3 = bd2; bj3 = bj2; bd2 = bd1; bj2 = bj1;
                bd1 = d; bj1 = jj;
            } else if (d < bd2) {
                bd4 = bd3; bj4 = bj3; bd3 = bd2; bj3 = bj2; bd2 = d; bj2 = jj;
            } else if (d < bd3) {
                bd4 = bd3; bj4 = bj3; bd3 = d; bj3 = jj;
            } else {
                bd4 = d; bj4 = jj;
            }
        }
    }
    size_t base = ((size_t)(b * NPTS + i) * NCH + c) * KNN;
    g_kd[base + 0] = bd0; g_kd[base + 1] = bd1; g_kd[base + 2] = bd2;
    g_kd[base + 3] = bd3; g_kd[base + 4] = bd4;
    g_kj[base + 0] = bj0; g_kj[base + 1] = bj1; g_kj[base + 2] = bj2;
    g_kj[base + 3] = bj3; g_kj[base + 4] = bj4;
}

// ---------------- KNN pass 2: merge 8 sorted 5-lists -> global top-5; count deg ----------------
__global__ void knn_merge_kernel() {
    int node = blockIdx.x * blockDim.x + threadIdx.x;
    int b = node >> 12;
    size_t base = (size_t)node * NCH * KNN;
    float hd[NCH];
    int hj[NCH], hp[NCH];
    #pragma unroll
    for (int c = 0; c < NCH; c++) {
        hd[c] = g_kd[base + c * KNN];
        hj[c] = g_kj[base + c * KNN];
        hp[c] = 0;
    }
    int out_base = node * KNN;
    int off = b * NPTS;
    #pragma unroll
    for (int r = 0; r < KNN; r++) {
        int best = 0;
        float d = hd[0];
        int j = hj[0];
        #pragma unroll
        for (int c = 1; c < NCH; c++) {
            if (hd[c] < d || (hd[c] == d && hj[c] < j)) { d = hd[c]; j = hj[c]; best = c; }
        }
        int nj = off + j;
        g_nbr[out_base + r] = nj;
        atomicAdd(&g_deg[nj], 1);
        int np = ++hp[best];
        if (np < KNN) {
            hd[best] = g_kd[base + best * KNN + np];
            hj[best] = g_kj[base + best * KNN + np];
        } else {
            hd[best] = 3.0e38f;
            hj[best] = 0x7fffffff;
        }
    }
}

__global__ void norm_kernel() {
    int i = blockIdx.x * blockDim.x + threadIdx.x;
    if (i < BNODES) g_norm[i] = rsqrtf(fmaxf((float)g_deg[i], 1.0f));
}

// ---------------- layer 1: 3 -> 64 pointwise + BN-affine + ReLU, split output ----------------
__global__ void layer1_kernel(const float* __restrict__ w1, const float* __restrict__ g1,
                              const float* __restrict__ b1) {
    int gid = blockIdx.x * blockDim.x + threadIdx.x;
    int node = gid >> 6;
    int o = gid & 63;
    const float* p = g_pts_sorted + node * 3;
    float a = p[0] * w1[o * 3 + 0] + p[1] * w1[o * 3 + 1] + p[2] * w1[o * 3 + 2];
    float v = fmaxf(a * g1[o] + b1[o], 0.0f);
    bf16 h = __float2bfloat16(v);
    size_t idx = (size_t)node * 64 + o;
    g_xh[idx] = h;
    g_xl[idx] = __float2bfloat16(v - __bfloat162float(h));
}

// ================= HMMA GEMM v3: cp.async pipelined, pre-split bf16 hi/lo =================
// OUT_MODE: 0 = fp32 C, 1 = split bf16 Ch/Cl, 2 = fused channel max-pool into g_pool.
// NSTAGE: smem pipeline stages (1 for K=64 single-chunk, 2 for K>=128).
template <int BN, int OUT_MODE, int NSTAGE>
__global__ void __launch_bounds__(256, 1)
hmma_gemm3(const bf16* __restrict__ Ah, const bf16* __restrict__ Al,
           const bf16* __restrict__ Wh, const bf16* __restrict__ Wl,
           float* __restrict__ C, bf16* __restrict__ Ch, bf16* __restrict__ Cl,
           int M, int N, int K,
           const float* __restrict__ gamma, const float* __restrict__ beta,
           const float* __restrict__ rowscale, int do_relu) {
    extern __shared__ char sm_raw[];
    __shared__ unsigned spool[128];
    uint32_t raw_s = smem_u32(sm_raw);
    uint32_t base_s = (raw_s + 1023u) & ~1023u;
    char* dsm = sm_raw + (base_s - raw_s);

    constexpr int ABYTES = 128 * 64 * 2;
    constexpr int BBYTES = BN * 64 * 2;
    constexpr int STAGE = 2 * ABYTES + 2 * BBYTES;
    constexpr int NI = BN / 32;
    constexpr int WN = BN / 4;

    int tid = threadIdx.x;
    int lane = tid & 31;
    int wid = tid >> 5;
    int wm = wid >> 2;
    int wn = wid & 3;
    int m0 = blockIdx.y * 128;
    int n0 = blockIdx.x * BN;

    if (OUT_MODE == 2 && tid < BN) spool[tid] = 0u;

    auto copy_chunk = [&](int cc, char* st) {
        char* pAh = st;
        char* pAl = pAh + ABYTES;
        char* pBh = pAl + ABYTES;
        char* pBl = pBh + BBYTES;
        int k0g = cc << 6;
        #pragma unroll
        for (int i = 0; i < 4; i++) {
            int g = tid + i * 256;
            int row = g >> 3, kg = g & 7;
            size_t src = (size_t)(m0 + row) * K + k0g + kg * 8;
            uint32_t off = SW128((uint32_t)(row * 128 + kg * 16));
            cp16(smem_u32(pAh + off), Ah + src);
            cp16(smem_u32(pAl + off), Al + src);
        }
        #pragma unroll
        for (int i = 0; i < (BN * 8) / 256; i++) {
            int g = tid + i * 256;
            int row = g >> 3, kg = g & 7;
            size_t src = (size_t)(n0 + row) * K + k0g + kg * 8;
            uint32_t off = SW128((uint32_t)(row * 128 + kg * 16));
            cp16(smem_u32(pBh + off), Wh + src);
            cp16(smem_u32(pBl + off), Wl + src);
        }
    };

    float acc[4][NI][4];
    #pragma unroll
    for (int mi = 0; mi < 4; mi++)
        #pragma unroll
        for (int ni = 0; ni < NI; ni++)
            #pragma unroll
            for (int r = 0; r < 4; r++) acc[mi][ni][r] = 0.0f;

    int nchunks = K >> 6;
    copy_chunk(0, dsm);
    CP_COMMIT();

    for (int c = 0; c < nchunks; c++) {
        char* st = dsm + (c % NSTAGE) * STAGE;
        if (NSTAGE == 1 && c > 0) { copy_chunk(c, st); CP_COMMIT(); }
        CP_WAIT0();
        __syncthreads();
        if (NSTAGE > 1 && c + 1 < nchunks) {
            copy_chunk(c + 1, dsm + ((c + 1) % NSTAGE) * STAGE);
            CP_COMMIT();
        }
        uint32_t sAh = smem_u32(st);
        uint32_t sAl = sAh + ABYTES;
        uint32_t sBh = sAl + ABYTES;
        uint32_t sBl = sBh + BBYTES;

        #pragma unroll
        for (int kk = 0; kk < 4; kk++) {
            int k0 = kk * 16;
            uint32_t aH[4][4], aL[4][4], bH[NI][2], bL[NI][2];
            #pragma unroll
            for (int mi = 0; mi < 4; mi++) {
                int row = wm * 64 + mi * 16 + (lane & 15);
                uint32_t off = SW128((uint32_t)(row * 128 + (k0 + ((lane >> 4) << 3)) * 2));
                ldsm_x4(aH[mi], sAh + off);
                ldsm_x4(aL[mi], sAl + off);
            }
            #pragma unroll
            for (int ni = 0; ni < NI; ni++) {
                int nrow = wn * WN + ni * 8 + (lane & 7);
                uint32_t off = SW128((uint32_t)(nrow * 128 + (k0 + (((lane >> 3) & 1) << 3)) * 2));
                ldsm_x2(bH[ni], sBh + off);
                ldsm_x2(bL[ni], sBl + off);
            }
            #pragma unroll
            for (int mi = 0; mi < 4; mi++)
                #pragma unroll
                for (int ni = 0; ni < NI; ni++) {
                    mma16816(acc[mi][ni], aH[mi], bH[ni]);
                    mma16816(acc[mi][ni], aH[mi], bL[ni]);
                    mma16816(acc[mi][ni], aL[mi], bH[ni]);
                }
        }
        __syncthreads();
    }

    // ---- epilogue ----
    float pmax[NI][2];
    if (OUT_MODE == 2) {
        #pragma unroll
        for (int ni = 0; ni < NI; ni++) { pmax[ni][0] = 0.0f; pmax[ni][1] = 0.0f; }
    }
    #pragma unroll
    for (int mi = 0; mi < 4; mi++) {
        int r0 = m0 + wm * 64 + mi * 16 + (lane >> 2);
        int r1 = r0 + 8;
        float rs0 = rowscale ? rowscale[r0] : 1.0f;
        float rs1 = rowscale ? rowscale[r1] : 1.0f;
        #pragma unroll
        for (int ni = 0; ni < NI; ni++) {
            int cN = n0 + wn * WN + ni * 8 + (lane & 3) * 2;
            float gm0 = 1.0f, gm1 = 1.0f, be0 = 0.0f, be1 = 0.0f;
            if (gamma) { gm0 = gamma[cN]; gm1 = gamma[cN + 1]; be0 = beta[cN]; be1 = beta[cN + 1]; }
            float x0 = acc[mi][ni][0] * rs0 * gm0 + be0;
            float x1 = acc[mi][ni][1] * rs0 * gm1 + be1;
            float x2 = acc[mi][ni][2] * rs1 * gm0 + be0;
            float x3 = acc[mi][ni][3] * rs1 * gm1 + be1;
            if (do_relu) {
                x0 = fmaxf(x0, 0.0f); x1 = fmaxf(x1, 0.0f);
                x2 = fmaxf(x2, 0.0f); x3 = fmaxf(x3, 0.0f);
            }
            if (OUT_MODE == 0) {
                *(float2*)(C + (size_t)r0 * N + cN) = make_float2(x0, x1);
                *(float2*)(C + (size_t)r1 * N + cN) = make_float2(x2, x3);
            } else if (OUT_MODE == 1) {
                uint32_t h01, l01, h23, l23;
                split2(x0, x1, h01, l01);
                split2(x2, x3, h23, l23);
                *(uint32_t*)(Ch + (size_t)r0 * N + cN) = h01;
                *(uint32_t*)(Cl + (size_t)r0 * N + cN) = l01;
                *(uint32_t*)(Ch + (size_t)r1 * N + cN) = h23;
                *(uint32_t*)(Cl + (size_t)r1 * N + cN) = l23;
            } else {
                pmax[ni][0] = fmaxf(pmax[ni][0], fmaxf(x0, x2));
                pmax[ni][1] = fmaxf(pmax[ni][1], fmaxf(x1, x3));
            }
        }
    }
    if (OUT_MODE == 2) {
        #pragma unroll
        for (int ni = 0; ni < NI; ni++) {
            int col = wn * WN + ni * 8 + (lane & 3) * 2;
            atomicMax(&spool[col], __float_as_uint(pmax[ni][0]));
            atomicMax(&spool[col + 1], __float_as_uint(pmax[ni][1]));
        }
        __syncthreads();
        if (tid < BN) atomicMax(&g_pool[n0 + tid], spool[tid]);
    }
}

// ---------------- GCN aggregate: split-output version ----------------
__global__ void agg_kernel(const float* __restrict__ hw, const float* __restrict__ bias,
                           bf16* __restrict__ Ch, bf16* __restrict__ Cl, int F, int do_relu) {
    size_t gid = (size_t)blockIdx.x * blockDim.x + threadIdx.x;
    int node = (int)(gid / F);
    int f = (int)(gid - (size_t)node * F);
    const int* nb = g_nbr + node * KNN;
    float s = hw[(size_t)nb[0] * F + f];
    s += hw[(size_t)nb[1] * F + f];
    s += hw[(size_t)nb[2] * F + f];
    s += hw[(size_t)nb[3] * F + f];
    s += hw[(size_t)nb[4] * F + f];
    float v = s * 0.44721359549995793f + bias[f];   // rsqrt(5) == norm_in (deg_in == 5 always)
    if (do_relu) v = fmaxf(v, 0.0f);
    bf16 h = __float2bfloat16(v);
    Ch[gid] = h;
    Cl[gid] = __float2bfloat16(v - __bfloat162float(h));
}

// ---------------- final linear 256 -> 128 ----------------
__global__ void final_kernel(const float* __restrict__ fc3_w, const float* __restrict__ fc3_b,
                             float* __restrict__ out) {
    int o = threadIdx.x;
    float s = 0.0f;
    #pragma unroll 8
    for (int k = 0; k < 256; k++)
        s += __uint_as_float(g_pool[k]) * fc3_w[o * 256 + k];
    out[o] = s + fc3_b[o];
}

// ---------------- orchestration ----------------
extern "C" void kernel_launch(void* const* d_in, const int* in_sizes, int n_in,
                              void* d_out, int out_size) {
    const float* pts  = (const float*)d_in[0];
    const float* w1   = (const float*)d_in[1];
    const float* g1   = (const float*)d_in[2];
    const float* b1   = (const float*)d_in[3];
    const float* w2   = (const float*)d_in[4];
    const float* g2   = (const float*)d_in[5];
    const float* b2   = (const float*)d_in[6];
    const float* w3   = (const float*)d_in[7];
    const float* g3   = (const float*)d_in[8];
    const float* b3   = (const float*)d_in[9];
    const float* w4   = (const float*)d_in[10];
    const float* g4   = (const float*)d_in[11];
    const float* b4   = (const float*)d_in[12];
    const float* gc1w = (const float*)d_in[13];
    const float* gc1b = (const float*)d_in[14];
    const float* gc2w = (const float*)d_in[15];
    const float* gc2b = (const float*)d_in[16];
    const float* gc3w = (const float*)d_in[17];
    const float* gc3b = (const float*)d_in[18];
    const float* fc1w = (const float*)d_in[19];
    const float* bf1g = (const float*)d_in[20];
    const float* bf1b = (const float*)d_in[21];
    const float* fc2w = (const float*)d_in[22];
    const float* bf2g = (const float*)d_in[23];
    const float* bf2b = (const float*)d_in[24];
    const float* fc3w = (const float*)d_in[25];
    const float* fc3b = (const float*)d_in[26];
    float* out = (float*)d_out;

    void* p;
    cudaGetSymbolAddress(&p, g_bufA);  float* bufA = (float*)p;
    cudaGetSymbolAddress(&p, g_norm);  float* normp = (float*)p;
    cudaGetSymbolAddress(&p, g_xh);    bf16* xh = (bf16*)p;
    cudaGetSymbolAddress(&p, g_xl);    bf16* xl = (bf16*)p;
    cudaGetSymbolAddress(&p, g_yh);    bf16* yh = (bf16*)p;
    cudaGetSymbolAddress(&p, g_yl);    bf16* yl = (bf16*)p;
    cudaGetSymbolAddress(&p, g_wh);    bf16* wh = (bf16*)p;
    cudaGetSymbolAddress(&p, g_wl);    bf16* wl = (bf16*)p;

    const int ST64  = 2 * 128 * 64 * 2 + 2 * 64 * 64 * 2;    // 49152
    const int ST128 = 2 * 128 * 64 * 2 + 2 * 128 * 64 * 2;   // 65536
    const int SM64_1  = ST64 + 1024;
    const int SM128_1 = ST128 + 1024;
    const int SM128_2 = 2 * ST128 + 1024;                     // 132096
    cudaFuncSetAttribute(hmma_gemm3<64, 1, 1>,  cudaFuncAttributeMaxDynamicSharedMemorySize, SM64_1);
    cudaFuncSetAttribute(hmma_gemm3<128, 1, 1>, cudaFuncAttributeMaxDynamicSharedMemorySize, SM128_1);
    cudaFuncSetAttribute(hmma_gemm3<128, 0, 2>, cudaFuncAttributeMaxDynamicSharedMemorySize, SM128_2);
    cudaFuncSetAttribute(hmma_gemm3<128, 1, 2>, cudaFuncAttributeMaxDynamicSharedMemorySize, SM128_2);
    cudaFuncSetAttribute(hmma_gemm3<128, 2, 2>, cudaFuncAttributeMaxDynamicSharedMemorySize, SM128_2);

    const int M = BNODES;

    init_kernel<<<(BNODES + 255) / 256, 256>>>();

    WSegs S;
    S.src[0] = w2;   S.dst[0] = OFF_W2;  S.K[0] = 64;  S.N[0] = 64;  S.trans[0] = 0; S.cnt[0] = 4096;
    S.src[1] = w3;   S.dst[1] = OFF_W3;  S.K[1] = 64;  S.N[1] = 64;  S.trans[1] = 0; S.cnt[1] = 4096;
    S.src[2] = w4;   S.dst[2] = OFF_W4;  S.K[2] = 64;  S.N[2] = 128; S.trans[2] = 0; S.cnt[2] = 8192;
    S.src[3] = gc1w; S.dst[3] = OFF_GC1; S.K[3] = 128; S.N[3] = 128; S.trans[3] = 1; S.cnt[3] = 16384;
    S.src[4] = gc2w; S.dst[4] = OFF_GC2; S.K[4] = 128; S.N[4] = 128; S.trans[4] = 1; S.cnt[4] = 16384;
    S.src[5] = gc3w; S.dst[5] = OFF_GC3; S.K[5] = 128; S.N[5] = 256; S.trans[5] = 1; S.cnt[5] = 32768;
    S.src[6] = fc1w; S.dst[6] = OFF_FC1; S.K[6] = 256; S.N[6] = 512; S.trans[6] = 0; S.cnt[6] = 131072;
    S.src[7] = fc2w; S.dst[7] = OFF_FC2; S.K[7] = 512; S.N[7] = 256; S.trans[7] = 0; S.cnt[7] = 131072;
    wprep_all<<<344064 / 256, 256>>>(S);

    prep_kernel<<<NBATCH, 256>>>(pts);
    sort_warp_kernel<<<dim3(NBATCH, NPTS / 64), 256>>>(pts);
    knn_part_kernel<<<dim3(NBATCH, 16 * NCH), 256>>>(pts);
    knn_merge_kernel<<<BNODES / 256, 256>>>();
    norm_kernel<<<(BNODES + 255) / 256, 256>>>();

    // local conv stack (split-in, split-out)
    layer1_kernel<<<(BNODES * 64) / 256, 256>>>(w1, g1, b1);
    hmma_gemm3<64, 1, 1><<<dim3(1, M / 128), 256, SM64_1>>>(
        xh, xl, wh + OFF_W2, wl + OFF_W2, nullptr, yh, yl, M, 64, 64, g2, b2, nullptr, 1);
    hmma_gemm3<64, 1, 1><<<dim3(1, M / 128), 256, SM64_1>>>(
        yh, yl, wh + OFF_W3, wl + OFF_W3, nullptr, xh, xl, M, 64, 64, g3, b3, nullptr, 1);
    hmma_gemm3<128, 1, 1><<<dim3(1, M / 128), 256, SM128_1>>>(
        xh, xl, wh + OFF_W4, wl + OFF_W4, nullptr, yh, yl, M, 128, 64, g4, b4, nullptr, 1);

    // GCN layers
    hmma_gemm3<128, 0, 2><<<dim3(1, M / 128), 256, SM128_2>>>(
        yh, yl, wh + OFF_GC1, wl + OFF_GC1, bufA, nullptr, nullptr, M, 128, 128, nullptr, nullptr, normp, 0);
    agg_kernel<<<(M * 128) / 256, 256>>>(bufA, gc1b, xh, xl, 128, 1);
    hmma_gemm3<128, 0, 2><<<dim3(1, M / 128), 256, SM128_2>>>(
        xh, xl, wh + OFF_GC2, wl + OFF_GC2, bufA, nullptr, nullptr, M, 128, 128, nullptr, nullptr, normp, 0);
    agg_kernel<<<(M * 128) / 256, 256>>>(bufA, gc2b, yh, yl, 128, 1);
    hmma_gemm3<128, 0, 2><<<dim3(2, M / 128), 256, SM128_2>>>(
        yh, yl, wh + OFF_GC3, wl + OFF_GC3, bufA, nullptr, nullptr, M, 256, 128, nullptr, nullptr, normp, 0);
    agg_kernel<<<(M * 256) / 256, 256>>>(bufA, gc3b, xh, xl, 256, 0);

    // head
    hmma_gemm3<128, 1, 2><<<dim3(4, M / 128), 256, SM128_2>>>(
        xh, xl, wh + OFF_FC1, wl + OFF_FC1, nullptr, yh, yl, M, 512, 256, bf1g, bf1b, nullptr, 1);
    hmma_gemm3<128, 2, 2><<<dim3(2, M / 128), 256, SM128_2>>>(
        yh, yl, wh + OFF_FC2, wl + OFF_FC2, nullptr, nullptr, nullptr, M, 256, 512, bf2g, bf2b, nullptr, 1);

    final_kernel<<<1, 128>>>(fc3w, fc3b, out);
}